// round 5
// baseline (speedup 1.0000x reference)
#include <cuda_runtime.h>
#include <math.h>

// ---------------- static dims ----------------
#define NN    4096
#define FIN   512
#define HIDN  256
#define RRE   16
#define EE    65536
#define BBS   32
#define SSEQ  128
#define DHH   768
#define DD2   1536
#define GG4   3072

// ---------------- device scratch ----------------
__device__ float g_hrel[(size_t)RRE * NN * HIDN];
__device__ float g_out1[(size_t)NN * HIDN];
__device__ float g_cnt[(size_t)NN * RRE];
__device__ float g_agg[(size_t)NN * HIDN];
__device__ float g_out2[(size_t)NN * HIDN];
__device__ float g_x0[(size_t)NN * DHH];
__device__ float g_g0[(size_t)2 * NN * GG4];
__device__ float g_h0[(size_t)NN * DD2];
__device__ float g_g1[(size_t)2 * NN * GG4];
__device__ float g_M[(size_t)NN * DD2];
__device__ float g_st[3 * 2 * BBS * DHH];
__device__ float g_X[(size_t)NN * DD2];
__device__ float g_att[(size_t)NN * DD2];

__global__ void fill_zero_kernel(float* p, int n) {
    int i = blockIdx.x * 256 + threadIdx.x;
    if (i < n) p[i] = 0.0f;
}

__device__ __forceinline__ float sigf(float x) { return 1.0f / (1.0f + expf(-x)); }

// ---------------- generic tiled SGEMM ----------------
// C[M,N] = act( A @ (TRANSB ? B^T : B) + bias + (addC ? C : 0) ), batched over z.
// M,N multiples of 64; K multiple of 16.
template<bool TRANSB, bool RELU>
__global__ __launch_bounds__(256) void sgemm_kernel(
    const float* __restrict__ A, const float* __restrict__ B,
    const float* __restrict__ bias, float* __restrict__ C,
    int M, int N, int K,
    size_t sA, size_t sB, size_t sBias, size_t sC, int addC)
{
    A += (size_t)blockIdx.z * sA;
    B += (size_t)blockIdx.z * sB;
    C += (size_t)blockIdx.z * sC;
    const float* bi = bias ? bias + (size_t)blockIdx.z * sBias : (const float*)0;

    __shared__ float As[16][65];
    __shared__ float Bs[16][65];
    const int m0 = blockIdx.y * 64, n0 = blockIdx.x * 64;
    const int tid = threadIdx.x;
    const int tm = (tid >> 4) * 4;
    const int tn = (tid & 15) * 4;
    float acc[4][4];
#pragma unroll
    for (int i = 0; i < 4; i++)
#pragma unroll
        for (int j = 0; j < 4; j++) acc[i][j] = 0.0f;

    for (int k0 = 0; k0 < K; k0 += 16) {
        {
            int am = tid >> 2, ak = (tid & 3) * 4;
            float4 v = *(const float4*)(A + (size_t)(m0 + am) * K + k0 + ak);
            As[ak + 0][am] = v.x; As[ak + 1][am] = v.y;
            As[ak + 2][am] = v.z; As[ak + 3][am] = v.w;
        }
        if (TRANSB) {
            int bn = tid >> 2, bk = (tid & 3) * 4;
            float4 v = *(const float4*)(B + (size_t)(n0 + bn) * K + k0 + bk);
            Bs[bk + 0][bn] = v.x; Bs[bk + 1][bn] = v.y;
            Bs[bk + 2][bn] = v.z; Bs[bk + 3][bn] = v.w;
        } else {
            int bk = tid >> 4, bn = (tid & 15) * 4;
            float4 v = *(const float4*)(B + (size_t)(k0 + bk) * N + n0 + bn);
            Bs[bk][bn + 0] = v.x; Bs[bk][bn + 1] = v.y;
            Bs[bk][bn + 2] = v.z; Bs[bk][bn + 3] = v.w;
        }
        __syncthreads();
#pragma unroll
        for (int kk = 0; kk < 16; kk++) {
            float a0 = As[kk][tm], a1 = As[kk][tm + 1], a2 = As[kk][tm + 2], a3 = As[kk][tm + 3];
            float b0 = Bs[kk][tn], b1 = Bs[kk][tn + 1], b2 = Bs[kk][tn + 2], b3 = Bs[kk][tn + 3];
            acc[0][0] += a0 * b0; acc[0][1] += a0 * b1; acc[0][2] += a0 * b2; acc[0][3] += a0 * b3;
            acc[1][0] += a1 * b0; acc[1][1] += a1 * b1; acc[1][2] += a1 * b2; acc[1][3] += a1 * b3;
            acc[2][0] += a2 * b0; acc[2][1] += a2 * b1; acc[2][2] += a2 * b2; acc[2][3] += a2 * b3;
            acc[3][0] += a3 * b0; acc[3][1] += a3 * b1; acc[3][2] += a3 * b2; acc[3][3] += a3 * b3;
        }
        __syncthreads();
    }
#pragma unroll
    for (int i = 0; i < 4; i++) {
#pragma unroll
        for (int j = 0; j < 4; j++) {
            size_t idx = (size_t)(m0 + tm + i) * N + n0 + tn + j;
            float v = acc[i][j];
            if (bi) v += bi[n0 + tn + j];
            if (addC) v += C[idx];
            if (RELU) v = fmaxf(v, 0.0f);
            C[idx] = v;
        }
    }
}

// ---------------- graph kernels ----------------
__global__ void count_kernel(const int* __restrict__ ei, const int* __restrict__ et,
                             float* __restrict__ cnt) {
    int e = blockIdx.x * 256 + threadIdx.x;
    if (e < EE) atomicAdd(&cnt[ei[EE + e] * RRE + et[e]], 1.0f);
}

__global__ void rgcn_scatter_kernel(const float* __restrict__ hrel, const int* __restrict__ ei,
                                    const int* __restrict__ et, const float* __restrict__ cnt,
                                    float* __restrict__ out1) {
    int e = blockIdx.x * 4 + (threadIdx.x >> 6);
    int lane = threadIdx.x & 63;
    int src = ei[e], dst = ei[EE + e], r = et[e];
    float inv = 1.0f / fmaxf(cnt[dst * RRE + r], 1.0f);
    float4 v = ((const float4*)(hrel + ((size_t)r * NN + src) * HIDN))[lane];
    float* o = out1 + (size_t)dst * HIDN + lane * 4;
    atomicAdd(o + 0, v.x * inv);
    atomicAdd(o + 1, v.y * inv);
    atomicAdd(o + 2, v.z * inv);
    atomicAdd(o + 3, v.w * inv);
}

__global__ void gconv_scatter_kernel(const float* __restrict__ out1, const int* __restrict__ ei,
                                     float* __restrict__ agg) {
    int e = blockIdx.x * 4 + (threadIdx.x >> 6);
    int lane = threadIdx.x & 63;
    int src = ei[e], dst = ei[EE + e];
    float4 v = ((const float4*)(out1 + (size_t)src * HIDN))[lane];
    float* o = agg + (size_t)dst * HIDN + lane * 4;
    atomicAdd(o + 0, v.x);
    atomicAdd(o + 1, v.y);
    atomicAdd(o + 2, v.z);
    atomicAdd(o + 3, v.w);
}

// x0[(s*B+b)] = [features[b*S+s], out2[b*S+s]]
__global__ void concat_kernel(const float* __restrict__ feat, const float* __restrict__ out2,
                              float* __restrict__ x0) {
    int n = blockIdx.x;
    int b = n >> 7, s = n & 127;
    float* dstrow = x0 + (size_t)(s * BBS + b) * DHH;
    for (int d = threadIdx.x; d < DHH; d += 256)
        dstrow[d] = (d < FIN) ? feat[(size_t)n * FIN + d] : out2[(size_t)n * HIDN + (d - FIN)];
}

// One BiLSTM timestep, both directions. Grid (96, 2), 256 thr.
// Thread (jj=tid>>5, b=tid&31) owns hidden unit j0+jj of batch b.
__global__ __launch_bounds__(256) void lstm_step_kernel(
    const float* __restrict__ Whh,    // [2][3072][768]
    const float* __restrict__ gpre,   // [2][4096][3072]
    float* __restrict__ state,        // hbuf0 | hbuf1 | c  (each 2*32*768)
    float* __restrict__ hout,         // [4096][1536]
    int t)
{
    const int d = blockIdx.y;
    const int j0 = blockIdx.x * 8;
    const int tid = threadIdx.x;
    const int jj = tid >> 5, b = tid & 31;
    const int tdir = (d == 0) ? t : (SSEQ - 1 - t);
    const float* hin = state + (t & 1) * (2 * BBS * DHH) + d * (BBS * DHH);
    float* hOut = state + ((t + 1) & 1) * (2 * BBS * DHH) + d * (BBS * DHH);
    float* cst = state + 2 * (2 * BBS * DHH) + d * (BBS * DHH);
    const float* Wb = Whh + (size_t)d * GG4 * DHH;

    __shared__ float Wsm[32][33];
    __shared__ float Hsm[32][33];
    float acc0 = 0.f, acc1 = 0.f, acc2 = 0.f, acc3 = 0.f;
    const int lkk = tid & 31;
    const int lrb = (tid >> 5) * 4;

    for (int k0 = 0; k0 < DHH; k0 += 32) {
#pragma unroll
        for (int i = 0; i < 4; i++) {
            int r = lrb + i;
            int grow = j0 + (r & 7) + ((r >> 3) * DHH);
            Wsm[r][lkk] = Wb[(size_t)grow * DHH + k0 + lkk];
            Hsm[r][lkk] = hin[r * DHH + k0 + lkk];
        }
        __syncthreads();
#pragma unroll
        for (int kk = 0; kk < 32; kk++) {
            float hv = Hsm[b][kk];
            acc0 += Wsm[jj][kk] * hv;
            acc1 += Wsm[jj + 8][kk] * hv;
            acc2 += Wsm[jj + 16][kk] * hv;
            acc3 += Wsm[jj + 24][kk] * hv;
        }
        __syncthreads();
    }
    int row = tdir * BBS + b;
    int j = j0 + jj;
    const float* gp = gpre + ((size_t)d * NN + row) * GG4;
    float gi = acc0 + gp[j];
    float gf = acc1 + gp[DHH + j];
    float gg = acc2 + gp[2 * DHH + j];
    float go = acc3 + gp[3 * DHH + j];
    float c = cst[b * DHH + j];
    c = sigf(gf) * c + sigf(gi) * tanhf(gg);
    float h = sigf(go) * tanhf(c);
    cst[b * DHH + j] = c;
    hOut[b * DHH + j] = h;
    hout[(size_t)row * DD2 + d * DHH + j] = h;
}

// MatchingAttention: fused scores->tanh->masked softmax->weighted sum.
// Grid (8 t-tiles, 32 b), 256 threads.
__global__ __launch_bounds__(256) void attention_kernel(
    const float* __restrict__ M, const float* __restrict__ X,
    const float* __restrict__ umask, float* __restrict__ att)
{
    const int b = blockIdx.y;
    const int t0 = blockIdx.x * 16;
    const int tid = threadIdx.x;
    const int ti = tid >> 4, si = tid & 15;

    __shared__ float Ms[128][33];
    __shared__ float Xs[16][33];
    __shared__ float Aa[16][129];
    __shared__ float um[128];
    if (tid < 128) um[tid] = umask[b * SSEQ + tid];
    __syncthreads();

    float acc[8];
#pragma unroll
    for (int u = 0; u < 8; u++) acc[u] = 0.0f;

    // Phase 1: scores[t, s] = X[t,b,:] . (M[s,b,:] * um[s])
    for (int k0 = 0; k0 < DD2; k0 += 32) {
        {
            int s = tid >> 1;
            float u = um[s];
            const float* mrow = M + ((size_t)(s * BBS + b)) * DD2 + k0;
#pragma unroll
            for (int i = 0; i < 4; i++) {
                int c = (tid & 1) * 16 + i * 4;
                float4 v = *(const float4*)(mrow + c);
                Ms[s][c] = v.x * u; Ms[s][c + 1] = v.y * u;
                Ms[s][c + 2] = v.z * u; Ms[s][c + 3] = v.w * u;
            }
        }
        if (tid < 128) {
            int r = tid >> 3, c = (tid & 7) * 4;
            float4 v = *(const float4*)(X + ((size_t)((t0 + r) * BBS + b)) * DD2 + k0 + c);
            Xs[r][c] = v.x; Xs[r][c + 1] = v.y; Xs[r][c + 2] = v.z; Xs[r][c + 3] = v.w;
        }
        __syncthreads();
#pragma unroll
        for (int kk = 0; kk < 32; kk++) {
            float xv = Xs[ti][kk];
#pragma unroll
            for (int u = 0; u < 8; u++) acc[u] += xv * Ms[si * 8 + u][kk];
        }
        __syncthreads();
    }

    // tanh(score * um), softmax over s (16 threads per row), mask renorm
#pragma unroll
    for (int u = 0; u < 8; u++) acc[u] = tanhf(acc[u] * um[si * 8 + u]);
    float mx = -1e30f;
#pragma unroll
    for (int u = 0; u < 8; u++) mx = fmaxf(mx, acc[u]);
    for (int o = 8; o >= 1; o >>= 1) mx = fmaxf(mx, __shfl_xor_sync(0xffffffffu, mx, o, 16));
    float a[8]; float s2 = 0.0f;
#pragma unroll
    for (int u = 0; u < 8; u++) {
        a[u] = expf(acc[u] - mx) * um[si * 8 + u];
        s2 += a[u];
    }
    for (int o = 8; o >= 1; o >>= 1) s2 += __shfl_xor_sync(0xffffffffu, s2, o, 16);
    float inv = 1.0f / s2;
#pragma unroll
    for (int u = 0; u < 8; u++) Aa[ti][si * 8 + u] = a[u] * inv;
    __syncthreads();

    // Phase 2: att[t,b,:] = sum_s alpha[t,s] * M[s,b,:]
    for (int d0 = 0; d0 < DD2; d0 += 32) {
        {
            int s = tid >> 1;
            const float* mrow = M + ((size_t)(s * BBS + b)) * DD2 + d0;
#pragma unroll
            for (int i = 0; i < 4; i++) {
                int c = (tid & 1) * 16 + i * 4;
                float4 v = *(const float4*)(mrow + c);
                Ms[s][c] = v.x; Ms[s][c + 1] = v.y; Ms[s][c + 2] = v.z; Ms[s][c + 3] = v.w;
            }
        }
        __syncthreads();
        int dloc = (tid & 15) * 2;
        float r0 = 0.f, r1 = 0.f;
#pragma unroll 8
        for (int s = 0; s < 128; s++) {
            float al = Aa[ti][s];
            r0 += al * Ms[s][dloc];
            r1 += al * Ms[s][dloc + 1];
        }
        float* orow = att + ((size_t)((t0 + ti) * BBS + b)) * DD2 + d0 + dloc;
        orow[0] = r0; orow[1] = r1;
        __syncthreads();
    }
}

// ---------------- launch ----------------
extern "C" void kernel_launch(void* const* d_in, const int* in_sizes, int n_in,
                              void* d_out, int out_size) {
    const float* feat   = (const float*)d_in[0];
    const int*   ei     = (const int*)d_in[1];
    const int*   et     = (const int*)d_in[2];
    const float* umask  = (const float*)d_in[4];
    const float* Wrel   = (const float*)d_in[5];
    const float* Wroot  = (const float*)d_in[6];
    const float* rb     = (const float*)d_in[7];
    const float* gcWrel = (const float*)d_in[8];
    const float* gcWroot= (const float*)d_in[9];
    const float* gcb    = (const float*)d_in[10];
    const float* Wih0   = (const float*)d_in[11];
    const float* Whh0   = (const float*)d_in[12];
    const float* b0     = (const float*)d_in[13];
    const float* Wih1   = (const float*)d_in[14];
    const float* Whh1   = (const float*)d_in[15];
    const float* b1     = (const float*)d_in[16];
    const float* mattW  = (const float*)d_in[17];
    const float* mattb  = (const float*)d_in[18];
    const float* linW   = (const float*)d_in[19];
    const float* linb   = (const float*)d_in[20];
    float* out = (float*)d_out;

    float *hrel, *out1, *cnt, *agg, *out2, *x0, *g0, *h0, *g1, *Mb, *st, *Xb, *attb;
    cudaGetSymbolAddress((void**)&hrel, g_hrel);
    cudaGetSymbolAddress((void**)&out1, g_out1);
    cudaGetSymbolAddress((void**)&cnt,  g_cnt);
    cudaGetSymbolAddress((void**)&agg,  g_agg);
    cudaGetSymbolAddress((void**)&out2, g_out2);
    cudaGetSymbolAddress((void**)&x0,   g_x0);
    cudaGetSymbolAddress((void**)&g0,   g_g0);
    cudaGetSymbolAddress((void**)&h0,   g_h0);
    cudaGetSymbolAddress((void**)&g1,   g_g1);
    cudaGetSymbolAddress((void**)&Mb,   g_M);
    cudaGetSymbolAddress((void**)&st,   g_st);
    cudaGetSymbolAddress((void**)&Xb,   g_X);
    cudaGetSymbolAddress((void**)&attb, g_att);

    // --- graph stage ---
    fill_zero_kernel<<<(NN * RRE + 255) / 256, 256>>>(cnt, NN * RRE);
    fill_zero_kernel<<<(NN * HIDN + 255) / 256, 256>>>(agg, NN * HIDN);
    count_kernel<<<EE / 256, 256>>>(ei, et, cnt);
    sgemm_kernel<false, false><<<dim3(4, 64, 1), 256>>>(feat, Wroot, rb, out1,
        NN, HIDN, FIN, 0, 0, 0, 0, 0);
    sgemm_kernel<false, false><<<dim3(4, 64, RRE), 256>>>(feat, Wrel, nullptr, hrel,
        NN, HIDN, FIN, 0, (size_t)FIN * HIDN, 0, (size_t)NN * HIDN, 0);
    rgcn_scatter_kernel<<<EE / 4, 256>>>(hrel, ei, et, cnt, out1);
    gconv_scatter_kernel<<<EE / 4, 256>>>(out1, ei, agg);
    sgemm_kernel<false, false><<<dim3(4, 64, 1), 256>>>(agg, gcWrel, gcb, out2,
        NN, HIDN, HIDN, 0, 0, 0, 0, 0);
    sgemm_kernel<false, false><<<dim3(4, 64, 1), 256>>>(out1, gcWroot, nullptr, out2,
        NN, HIDN, HIDN, 0, 0, 0, 0, 1);
    concat_kernel<<<NN, 256>>>(feat, out2, x0);

    // --- BiLSTM layer 0 ---
    sgemm_kernel<true, false><<<dim3(48, 64, 2), 256>>>(x0, Wih0, b0, g0,
        NN, GG4, DHH, 0, (size_t)GG4 * DHH, GG4, (size_t)NN * GG4, 0);
    fill_zero_kernel<<<(3 * 2 * BBS * DHH + 255) / 256, 256>>>(st, 3 * 2 * BBS * DHH);
    for (int t = 0; t < SSEQ; t++)
        lstm_step_kernel<<<dim3(96, 2), 256>>>(Whh0, g0, st, h0, t);

    // --- BiLSTM layer 1 ---
    sgemm_kernel<true, false><<<dim3(48, 64, 2), 256>>>(h0, Wih1, b1, g1,
        NN, GG4, DD2, 0, (size_t)GG4 * DD2, GG4, (size_t)NN * GG4, 0);
    fill_zero_kernel<<<(3 * 2 * BBS * DHH + 255) / 256, 256>>>(st, 3 * 2 * BBS * DHH);
    for (int t = 0; t < SSEQ; t++)
        lstm_step_kernel<<<dim3(96, 2), 256>>>(Whh1, g1, st, Mb, t);

    // --- attention + output ---
    sgemm_kernel<true, false><<<dim3(24, 64, 1), 256>>>(Mb, mattW, mattb, Xb,
        NN, DD2, DD2, 0, 0, 0, 0, 0);
    attention_kernel<<<dim3(8, 32), 256>>>(Mb, Xb, umask, attb);
    sgemm_kernel<true, true><<<dim3(12, 64, 1), 256>>>(attb, linW, linb, out,
        NN, DHH, DD2, 0, 0, 0, 0, 0);
}

// round 6
// speedup vs baseline: 1.0680x; 1.0680x over previous
#include <cuda_runtime.h>
#include <math.h>

// ---------------- static dims ----------------
#define NN    4096
#define FIN   512
#define HIDN  256
#define RRE   16
#define EE    65536
#define BBS   32
#define SSEQ  128
#define DHH   768
#define DD2   1536
#define GG4   3072

typedef unsigned long long u64;

// ---------------- packed f32x2 helpers ----------------
__device__ __forceinline__ u64 ffma2(u64 a, u64 b, u64 c) {
    u64 d; asm("fma.rn.f32x2 %0, %1, %2, %3;" : "=l"(d) : "l"(a), "l"(b), "l"(c)); return d;
}
__device__ __forceinline__ u64 fpack2(float lo, float hi) {
    u64 r; asm("mov.b64 %0, {%1, %2};" : "=l"(r) : "f"(lo), "f"(hi)); return r;
}
__device__ __forceinline__ float2 funpack2(u64 v) {
    float2 f; asm("mov.b64 {%0, %1}, %2;" : "=f"(f.x), "=f"(f.y) : "l"(v)); return f;
}

// ---------------- device scratch ----------------
__device__ float g_hrel[(size_t)RRE * NN * HIDN];
__device__ float g_out1[(size_t)NN * HIDN];
__device__ float g_cnt[(size_t)NN * RRE];
__device__ float g_agg[(size_t)NN * HIDN];
__device__ float g_out2[(size_t)NN * HIDN];
__device__ float g_x0[(size_t)NN * DHH];
__device__ float g_g0[(size_t)2 * NN * GG4];
__device__ float g_h0[(size_t)NN * DD2];
__device__ float g_g1[(size_t)2 * NN * GG4];
__device__ float g_M[(size_t)NN * DD2];
__device__ float g_st[3 * 2 * BBS * DHH];
__device__ float g_X[(size_t)NN * DD2];
__device__ float g_att[(size_t)NN * DD2];

__global__ void fill_zero_kernel(float* p, int n) {
    int i = blockIdx.x * 256 + threadIdx.x;
    if (i < n) p[i] = 0.0f;
}

__device__ __forceinline__ float sigf(float x) { return 1.0f / (1.0f + expf(-x)); }

// ---------------- 128x128 f32x2 SGEMM ----------------
// C[M,N] = act( A @ (TRANSB ? B^T : B) + bias + (addC ? C : 0) ), batched over z.
// M,N multiples of 128; K multiple of 16.
template<bool TRANSB, bool RELU>
__global__ __launch_bounds__(256) void sgemm_kernel(
    const float* __restrict__ A, const float* __restrict__ B,
    const float* __restrict__ bias, float* __restrict__ C,
    int M, int N, int K,
    size_t sA, size_t sB, size_t sBias, size_t sC, int addC)
{
    A += (size_t)blockIdx.z * sA;
    B += (size_t)blockIdx.z * sB;
    C += (size_t)blockIdx.z * sC;
    const float* bi = bias ? bias + (size_t)blockIdx.z * sBias : (const float*)0;

    __shared__ __align__(16) u64 Ad[16][128];   // duplicated (a,a) pairs, 16KB
    __shared__ __align__(16) float Bs[16][128]; // 8KB
    const int m0 = blockIdx.y * 128, n0 = blockIdx.x * 128;
    const int tid = threadIdx.x;
    const int ty = tid >> 4;   // 0..15, owns rows m0+ty*8..+7
    const int tx = tid & 15;   // owns cols n0+tx*2+32u (u=0..3), float2 each

    u64 acc[8][4];
#pragma unroll
    for (int i = 0; i < 8; i++)
#pragma unroll
        for (int u = 0; u < 4; u++) acc[i][u] = 0ull;

    for (int k0 = 0; k0 < K; k0 += 16) {
        {   // A tile: row ar, k-half ak; store duplicated pairs
            int ar = tid >> 1, ak = (tid & 1) * 8;
            const float* ap = A + (size_t)(m0 + ar) * K + k0 + ak;
            float4 v0 = *(const float4*)ap;
            float4 v1 = *(const float4*)(ap + 4);
            Ad[ak + 0][ar] = fpack2(v0.x, v0.x);
            Ad[ak + 1][ar] = fpack2(v0.y, v0.y);
            Ad[ak + 2][ar] = fpack2(v0.z, v0.z);
            Ad[ak + 3][ar] = fpack2(v0.w, v0.w);
            Ad[ak + 4][ar] = fpack2(v1.x, v1.x);
            Ad[ak + 5][ar] = fpack2(v1.y, v1.y);
            Ad[ak + 6][ar] = fpack2(v1.z, v1.z);
            Ad[ak + 7][ar] = fpack2(v1.w, v1.w);
        }
        if (TRANSB) {
            int bn = tid >> 1, bk = (tid & 1) * 8;
            const float* bp = B + (size_t)(n0 + bn) * K + k0 + bk;
            float4 v0 = *(const float4*)bp;
            float4 v1 = *(const float4*)(bp + 4);
            Bs[bk + 0][bn] = v0.x; Bs[bk + 1][bn] = v0.y;
            Bs[bk + 2][bn] = v0.z; Bs[bk + 3][bn] = v0.w;
            Bs[bk + 4][bn] = v1.x; Bs[bk + 5][bn] = v1.y;
            Bs[bk + 6][bn] = v1.z; Bs[bk + 7][bn] = v1.w;
        } else {
            int bk = tid >> 4, bn = (tid & 15) * 8;
            const float* bp = B + (size_t)(k0 + bk) * N + n0 + bn;
            *(float4*)&Bs[bk][bn] = *(const float4*)bp;
            *(float4*)&Bs[bk][bn + 4] = *(const float4*)(bp + 4);
        }
        __syncthreads();
#pragma unroll
        for (int kk = 0; kk < 16; kk++) {
            u64 b[4];
#pragma unroll
            for (int u = 0; u < 4; u++)
                b[u] = *(const u64*)&Bs[kk][tx * 2 + 32 * u];
            const ulonglong2* ap2 = (const ulonglong2*)&Ad[kk][ty * 8];
#pragma unroll
            for (int i2 = 0; i2 < 4; i2++) {
                ulonglong2 av = ap2[i2];
#pragma unroll
                for (int u = 0; u < 4; u++) {
                    acc[i2 * 2][u]     = ffma2(av.x, b[u], acc[i2 * 2][u]);
                    acc[i2 * 2 + 1][u] = ffma2(av.y, b[u], acc[i2 * 2 + 1][u]);
                }
            }
        }
        __syncthreads();
    }
#pragma unroll
    for (int i = 0; i < 8; i++) {
        int m = m0 + ty * 8 + i;
#pragma unroll
        for (int u = 0; u < 4; u++) {
            int n = n0 + tx * 2 + 32 * u;
            float2 v = funpack2(acc[i][u]);
            if (bi) { v.x += bi[n]; v.y += bi[n + 1]; }
            float2* cp = (float2*)&C[(size_t)m * N + n];
            if (addC) { float2 o = *cp; v.x += o.x; v.y += o.y; }
            if (RELU) { v.x = fmaxf(v.x, 0.f); v.y = fmaxf(v.y, 0.f); }
            *cp = v;
        }
    }
}

// ---------------- graph kernels ----------------
__global__ void count_kernel(const int* __restrict__ ei, const int* __restrict__ et,
                             float* __restrict__ cnt) {
    int e = blockIdx.x * 256 + threadIdx.x;
    if (e < EE) atomicAdd(&cnt[ei[EE + e] * RRE + et[e]], 1.0f);
}

__global__ void rgcn_scatter_kernel(const float* __restrict__ hrel, const int* __restrict__ ei,
                                    const int* __restrict__ et, const float* __restrict__ cnt,
                                    float* __restrict__ out1) {
    int e = blockIdx.x * 4 + (threadIdx.x >> 6);
    int lane = threadIdx.x & 63;
    int src = ei[e], dst = ei[EE + e], r = et[e];
    float inv = 1.0f / fmaxf(cnt[dst * RRE + r], 1.0f);
    float4 v = ((const float4*)(hrel + ((size_t)r * NN + src) * HIDN))[lane];
    float* o = out1 + (size_t)dst * HIDN + lane * 4;
    atomicAdd(o + 0, v.x * inv);
    atomicAdd(o + 1, v.y * inv);
    atomicAdd(o + 2, v.z * inv);
    atomicAdd(o + 3, v.w * inv);
}

__global__ void gconv_scatter_kernel(const float* __restrict__ out1, const int* __restrict__ ei,
                                     float* __restrict__ agg) {
    int e = blockIdx.x * 4 + (threadIdx.x >> 6);
    int lane = threadIdx.x & 63;
    int src = ei[e], dst = ei[EE + e];
    float4 v = ((const float4*)(out1 + (size_t)src * HIDN))[lane];
    float* o = agg + (size_t)dst * HIDN + lane * 4;
    atomicAdd(o + 0, v.x);
    atomicAdd(o + 1, v.y);
    atomicAdd(o + 2, v.z);
    atomicAdd(o + 3, v.w);
}

// x0[(s*B+b)] = [features[b*S+s], out2[b*S+s]]
__global__ void concat_kernel(const float* __restrict__ feat, const float* __restrict__ out2,
                              float* __restrict__ x0) {
    int n = blockIdx.x;
    int b = n >> 7, s = n & 127;
    float* dstrow = x0 + (size_t)(s * BBS + b) * DHH;
    for (int d = threadIdx.x; d < DHH; d += 256)
        dstrow[d] = (d < FIN) ? feat[(size_t)n * FIN + d] : out2[(size_t)n * HIDN + (d - FIN)];
}

// One BiLSTM timestep, both directions, f32x2 gate-paired. Grid (96, 2), 256 thr.
// Thread (jj=tid>>5, b=tid&31) owns hidden unit j0+jj of batch b.
__global__ __launch_bounds__(256) void lstm_step_kernel(
    const float* __restrict__ Whh,    // [2][3072][768]
    const float* __restrict__ gpre,   // [2][4096][3072]
    float* __restrict__ state,        // hbuf0 | hbuf1 | c  (each 2*32*768)
    float* __restrict__ hout,         // [4096][1536]
    int t)
{
    const int d = blockIdx.y;
    const int j0 = blockIdx.x * 8;
    const int tid = threadIdx.x;
    const int jj = tid >> 5, b = tid & 31;
    const int tdir = (d == 0) ? t : (SSEQ - 1 - t);
    const float* hin = state + (t & 1) * (2 * BBS * DHH) + d * (BBS * DHH);
    float* hOut = state + ((t + 1) & 1) * (2 * BBS * DHH) + d * (BBS * DHH);
    float* cst = state + 2 * (2 * BBS * DHH) + d * (BBS * DHH);
    const float* Wb = Whh + (size_t)d * GG4 * DHH;

    __shared__ u64 Wif[8][33];   // (W_i, W_f) pairs
    __shared__ u64 Wgo[8][33];   // (W_g, W_o) pairs
    __shared__ u64 Hd[32][33];   // (h, h) duplicated

    u64 pIF = 0ull, pGO = 0ull;
    const int wkk = tid & 31, wjj = tid >> 5;

    for (int k0 = 0; k0 < DHH; k0 += 32) {
        {   // W pair fill: 4 coalesced LDG.32 per thread
            int jg = j0 + wjj;
            size_t ck = (size_t)(k0 + wkk);
            Wif[wjj][wkk] = fpack2(Wb[(size_t)jg * DHH + ck],
                                   Wb[(size_t)(DHH + jg) * DHH + ck]);
            Wgo[wjj][wkk] = fpack2(Wb[(size_t)(2 * DHH + jg) * DHH + ck],
                                   Wb[(size_t)(3 * DHH + jg) * DHH + ck]);
        }
        {   // H duplicated fill
            int hr = tid >> 3, hk = (tid & 7) * 4;
            float4 v = *(const float4*)(hin + hr * DHH + k0 + hk);
            Hd[hr][hk + 0] = fpack2(v.x, v.x);
            Hd[hr][hk + 1] = fpack2(v.y, v.y);
            Hd[hr][hk + 2] = fpack2(v.z, v.z);
            Hd[hr][hk + 3] = fpack2(v.w, v.w);
        }
        __syncthreads();
#pragma unroll
        for (int kk = 0; kk < 32; kk++) {
            u64 hp = Hd[b][kk];
            pIF = ffma2(Wif[jj][kk], hp, pIF);
            pGO = ffma2(Wgo[jj][kk], hp, pGO);
        }
        __syncthreads();
    }
    float2 vif = funpack2(pIF);
    float2 vgo = funpack2(pGO);
    int row = tdir * BBS + b;
    int j = j0 + jj;
    const float* gp = gpre + ((size_t)d * NN + row) * GG4;
    float gi = vif.x + gp[j];
    float gf = vif.y + gp[DHH + j];
    float gg = vgo.x + gp[2 * DHH + j];
    float go = vgo.y + gp[3 * DHH + j];
    float c = cst[b * DHH + j];
    c = sigf(gf) * c + sigf(gi) * tanhf(gg);
    float h = sigf(go) * tanhf(c);
    cst[b * DHH + j] = c;
    hOut[b * DHH + j] = h;
    hout[(size_t)row * DD2 + d * DHH + j] = h;
}

// MatchingAttention: fused scores->tanh->masked softmax->weighted sum.
// Grid (8 t-tiles, 32 b), 256 threads.
__global__ __launch_bounds__(256) void attention_kernel(
    const float* __restrict__ M, const float* __restrict__ X,
    const float* __restrict__ umask, float* __restrict__ att)
{
    const int b = blockIdx.y;
    const int t0 = blockIdx.x * 16;
    const int tid = threadIdx.x;
    const int ti = tid >> 4, si = tid & 15;

    __shared__ float Ms[128][33];
    __shared__ float Xs[16][33];
    __shared__ float Aa[16][129];
    __shared__ float um[128];
    if (tid < 128) um[tid] = umask[b * SSEQ + tid];
    __syncthreads();

    float acc[8];
#pragma unroll
    for (int u = 0; u < 8; u++) acc[u] = 0.0f;

    for (int k0 = 0; k0 < DD2; k0 += 32) {
        {
            int s = tid >> 1;
            float u = um[s];
            const float* mrow = M + ((size_t)(s * BBS + b)) * DD2 + k0;
#pragma unroll
            for (int i = 0; i < 4; i++) {
                int c = (tid & 1) * 16 + i * 4;
                float4 v = *(const float4*)(mrow + c);
                Ms[s][c] = v.x * u; Ms[s][c + 1] = v.y * u;
                Ms[s][c + 2] = v.z * u; Ms[s][c + 3] = v.w * u;
            }
        }
        if (tid < 128) {
            int r = tid >> 3, c = (tid & 7) * 4;
            float4 v = *(const float4*)(X + ((size_t)((t0 + r) * BBS + b)) * DD2 + k0 + c);
            Xs[r][c] = v.x; Xs[r][c + 1] = v.y; Xs[r][c + 2] = v.z; Xs[r][c + 3] = v.w;
        }
        __syncthreads();
#pragma unroll
        for (int kk = 0; kk < 32; kk++) {
            float xv = Xs[ti][kk];
#pragma unroll
            for (int u = 0; u < 8; u++) acc[u] += xv * Ms[si * 8 + u][kk];
        }
        __syncthreads();
    }

#pragma unroll
    for (int u = 0; u < 8; u++) acc[u] = tanhf(acc[u] * um[si * 8 + u]);
    float mx = -1e30f;
#pragma unroll
    for (int u = 0; u < 8; u++) mx = fmaxf(mx, acc[u]);
    for (int o = 8; o >= 1; o >>= 1) mx = fmaxf(mx, __shfl_xor_sync(0xffffffffu, mx, o, 16));
    float a[8]; float s2 = 0.0f;
#pragma unroll
    for (int u = 0; u < 8; u++) {
        a[u] = expf(acc[u] - mx) * um[si * 8 + u];
        s2 += a[u];
    }
    for (int o = 8; o >= 1; o >>= 1) s2 += __shfl_xor_sync(0xffffffffu, s2, o, 16);
    float inv = 1.0f / s2;
#pragma unroll
    for (int u = 0; u < 8; u++) Aa[ti][si * 8 + u] = a[u] * inv;
    __syncthreads();

    for (int d0 = 0; d0 < DD2; d0 += 32) {
        {
            int s = tid >> 1;
            const float* mrow = M + ((size_t)(s * BBS + b)) * DD2 + d0;
#pragma unroll
            for (int i = 0; i < 4; i++) {
                int c = (tid & 1) * 16 + i * 4;
                float4 v = *(const float4*)(mrow + c);
                Ms[s][c] = v.x; Ms[s][c + 1] = v.y; Ms[s][c + 2] = v.z; Ms[s][c + 3] = v.w;
            }
        }
        __syncthreads();
        int dloc = (tid & 15) * 2;
        float r0 = 0.f, r1 = 0.f;
#pragma unroll 8
        for (int s = 0; s < 128; s++) {
            float al = Aa[ti][s];
            r0 += al * Ms[s][dloc];
            r1 += al * Ms[s][dloc + 1];
        }
        float* orow = att + ((size_t)((t0 + ti) * BBS + b)) * DD2 + d0 + dloc;
        orow[0] = r0; orow[1] = r1;
        __syncthreads();
    }
}

// ---------------- launch ----------------
extern "C" void kernel_launch(void* const* d_in, const int* in_sizes, int n_in,
                              void* d_out, int out_size) {
    const float* feat   = (const float*)d_in[0];
    const int*   ei     = (const int*)d_in[1];
    const int*   et     = (const int*)d_in[2];
    const float* umask  = (const float*)d_in[4];
    const float* Wrel   = (const float*)d_in[5];
    const float* Wroot  = (const float*)d_in[6];
    const float* rb     = (const float*)d_in[7];
    const float* gcWrel = (const float*)d_in[8];
    const float* gcWroot= (const float*)d_in[9];
    const float* gcb    = (const float*)d_in[10];
    const float* Wih0   = (const float*)d_in[11];
    const float* Whh0   = (const float*)d_in[12];
    const float* b0     = (const float*)d_in[13];
    const float* Wih1   = (const float*)d_in[14];
    const float* Whh1   = (const float*)d_in[15];
    const float* b1     = (const float*)d_in[16];
    const float* mattW  = (const float*)d_in[17];
    const float* mattb  = (const float*)d_in[18];
    const float* linW   = (const float*)d_in[19];
    const float* linb   = (const float*)d_in[20];
    float* out = (float*)d_out;

    float *hrel, *out1, *cnt, *agg, *out2, *x0, *g0, *h0, *g1, *Mb, *st, *Xb, *attb;
    cudaGetSymbolAddress((void**)&hrel, g_hrel);
    cudaGetSymbolAddress((void**)&out1, g_out1);
    cudaGetSymbolAddress((void**)&cnt,  g_cnt);
    cudaGetSymbolAddress((void**)&agg,  g_agg);
    cudaGetSymbolAddress((void**)&out2, g_out2);
    cudaGetSymbolAddress((void**)&x0,   g_x0);
    cudaGetSymbolAddress((void**)&g0,   g_g0);
    cudaGetSymbolAddress((void**)&h0,   g_h0);
    cudaGetSymbolAddress((void**)&g1,   g_g1);
    cudaGetSymbolAddress((void**)&Mb,   g_M);
    cudaGetSymbolAddress((void**)&st,   g_st);
    cudaGetSymbolAddress((void**)&Xb,   g_X);
    cudaGetSymbolAddress((void**)&attb, g_att);

    // --- graph stage ---
    fill_zero_kernel<<<(NN * RRE + 255) / 256, 256>>>(cnt, NN * RRE);
    fill_zero_kernel<<<(NN * HIDN + 255) / 256, 256>>>(agg, NN * HIDN);
    count_kernel<<<EE / 256, 256>>>(ei, et, cnt);
    sgemm_kernel<false, false><<<dim3(2, 32, 1), 256>>>(feat, Wroot, rb, out1,
        NN, HIDN, FIN, 0, 0, 0, 0, 0);
    sgemm_kernel<false, false><<<dim3(2, 32, RRE), 256>>>(feat, Wrel, nullptr, hrel,
        NN, HIDN, FIN, 0, (size_t)FIN * HIDN, 0, (size_t)NN * HIDN, 0);
    rgcn_scatter_kernel<<<EE / 4, 256>>>(hrel, ei, et, cnt, out1);
    gconv_scatter_kernel<<<EE / 4, 256>>>(out1, ei, agg);
    sgemm_kernel<false, false><<<dim3(2, 32, 1), 256>>>(agg, gcWrel, gcb, out2,
        NN, HIDN, HIDN, 0, 0, 0, 0, 0);
    sgemm_kernel<false, false><<<dim3(2, 32, 1), 256>>>(out1, gcWroot, nullptr, out2,
        NN, HIDN, HIDN, 0, 0, 0, 0, 1);
    concat_kernel<<<NN, 256>>>(feat, out2, x0);

    // --- BiLSTM layer 0 ---
    sgemm_kernel<true, false><<<dim3(24, 32, 2), 256>>>(x0, Wih0, b0, g0,
        NN, GG4, DHH, 0, (size_t)GG4 * DHH, GG4, (size_t)NN * GG4, 0);
    fill_zero_kernel<<<(3 * 2 * BBS * DHH + 255) / 256, 256>>>(st, 3 * 2 * BBS * DHH);
    for (int t = 0; t < SSEQ; t++)
        lstm_step_kernel<<<dim3(96, 2), 256>>>(Whh0, g0, st, h0, t);

    // --- BiLSTM layer 1 ---
    sgemm_kernel<true, false><<<dim3(24, 32, 2), 256>>>(h0, Wih1, b1, g1,
        NN, GG4, DD2, 0, (size_t)GG4 * DD2, GG4, (size_t)NN * GG4, 0);
    fill_zero_kernel<<<(3 * 2 * BBS * DHH + 255) / 256, 256>>>(st, 3 * 2 * BBS * DHH);
    for (int t = 0; t < SSEQ; t++)
        lstm_step_kernel<<<dim3(96, 2), 256>>>(Whh1, g1, st, Mb, t);

    // --- attention + output ---
    sgemm_kernel<true, false><<<dim3(12, 32, 1), 256>>>(Mb, mattW, mattb, Xb,
        NN, DD2, DD2, 0, 0, 0, 0, 0);
    attention_kernel<<<dim3(8, 32), 256>>>(Mb, Xb, umask, attb);
    sgemm_kernel<true, true><<<dim3(6, 32, 1), 256>>>(attb, linW, linb, out,
        NN, DHH, DD2, 0, 0, 0, 0, 0);
}

// round 8
// speedup vs baseline: 1.2329x; 1.1544x over previous
#include <cuda_runtime.h>
#include <math.h>

#define NN    4096
#define FIN   512
#define HIDN  256
#define RRE   16
#define EE    65536
#define BBS   32
#define SSEQ  128
#define DHH   768
#define DD2   1536
#define GG4   3072

typedef unsigned long long u64;
typedef unsigned int u32;

// ---------------- packed f32x2 + tf32 helpers ----------------
__device__ __forceinline__ u64 ffma2(u64 a, u64 b, u64 c) {
    u64 d; asm("fma.rn.f32x2 %0, %1, %2, %3;" : "=l"(d) : "l"(a), "l"(b), "l"(c)); return d;
}
__device__ __forceinline__ u64 fpack2(float lo, float hi) {
    u64 r; asm("mov.b64 %0, {%1, %2};" : "=l"(r) : "f"(lo), "f"(hi)); return r;
}
__device__ __forceinline__ float2 funpack2(u64 v) {
    float2 f; asm("mov.b64 {%0, %1}, %2;" : "=f"(f.x), "=f"(f.y) : "l"(v)); return f;
}
__device__ __forceinline__ u32 cvtf(float x) {
    u32 r; asm("cvt.rna.tf32.f32 %0, %1;" : "=r"(r) : "f"(x)); return r;
}
// split into hi (tf32) + lo (tf32 of residual) for 3xTF32 precision recovery
__device__ __forceinline__ void split_tf32(float x, u32& hi, u32& lo) {
    hi = cvtf(x);
    lo = cvtf(x - __uint_as_float(hi));
}
__device__ __forceinline__ void mma8(float* d, const u32* a, const u32* b) {
    asm("mma.sync.aligned.m16n8k8.row.col.f32.tf32.tf32.f32 "
        "{%0,%1,%2,%3}, {%4,%5,%6,%7}, {%8,%9}, {%0,%1,%2,%3};"
        : "+f"(d[0]), "+f"(d[1]), "+f"(d[2]), "+f"(d[3])
        : "r"(a[0]), "r"(a[1]), "r"(a[2]), "r"(a[3]), "r"(b[0]), "r"(b[1]));
}

// ---------------- device scratch ----------------
__device__ float g_hrel[(size_t)RRE * NN * HIDN];
__device__ float g_out1[(size_t)NN * HIDN];
__device__ float g_cnt[(size_t)NN * RRE];
__device__ float g_agg[(size_t)NN * HIDN];
__device__ float g_out2[(size_t)NN * HIDN];
__device__ float g_x0[(size_t)NN * DHH];
__device__ float g_g0[(size_t)2 * NN * GG4];
__device__ float g_h0[(size_t)NN * DD2];
__device__ float g_g1[(size_t)2 * NN * GG4];
__device__ float g_M[(size_t)NN * DD2];
__device__ float g_st[2 * 2 * BBS * DHH];
__device__ float g_X[(size_t)NN * DD2];
__device__ float g_att[(size_t)NN * DD2];
__device__ unsigned g_bar[2];   // cnt, gen

__global__ void fill_zero_kernel(float* p, int n) {
    int i = blockIdx.x * 256 + threadIdx.x;
    if (i < n) p[i] = 0.0f;
}

__device__ __forceinline__ float sigf(float x) { return 1.0f / (1.0f + expf(-x)); }

// ---------------- 3xTF32 tensor-core GEMM ----------------
// C[M,N] = act(A @ (TRANSB ? B^T : B) + bias + (addC ? C : 0)), z-batched.
// M mult of 128, N mult of 64, K mult of 16. fp32-accurate via hi/lo split.
template<bool TRANSB, bool RELU>
__global__ __launch_bounds__(256) void tgemm_kernel(
    const float* __restrict__ A, const float* __restrict__ B,
    const float* __restrict__ bias, float* __restrict__ C,
    int M, int N, int K,
    size_t sA, size_t sB, size_t sBias, size_t sC, int addC)
{
    A += (size_t)blockIdx.z * sA;
    B += (size_t)blockIdx.z * sB;
    C += (size_t)blockIdx.z * sC;
    const float* bi = bias ? bias + (size_t)blockIdx.z * sBias : (const float*)0;

    __shared__ u32 Ah[128][20];
    __shared__ u32 Al[128][20];
    __shared__ u32 Bh[16][76];
    __shared__ u32 Bl[16][76];
    const int m0 = blockIdx.y * 128, n0 = blockIdx.x * 64;
    const int tid = threadIdx.x;
    const int lane = tid & 31, wid = tid >> 5;
    const int wm = (wid & 3) * 32, wn = (wid >> 2) * 32;
    const int g = lane >> 2, tig = lane & 3;

    float acc[2][4][4];
#pragma unroll
    for (int mt = 0; mt < 2; mt++)
#pragma unroll
        for (int nt = 0; nt < 4; nt++)
#pragma unroll
            for (int q = 0; q < 4; q++) acc[mt][nt][q] = 0.0f;

    for (int k0 = 0; k0 < K; k0 += 16) {
        {   // A tile 128x16, hi/lo split
            int ar = tid >> 1, ak = (tid & 1) * 8;
            const float* ap = A + (size_t)(m0 + ar) * K + k0 + ak;
            float4 v0 = *(const float4*)ap, v1 = *(const float4*)(ap + 4);
            uint4 qh, ql;
            split_tf32(v0.x, qh.x, ql.x); split_tf32(v0.y, qh.y, ql.y);
            split_tf32(v0.z, qh.z, ql.z); split_tf32(v0.w, qh.w, ql.w);
            *(uint4*)&Ah[ar][ak] = qh; *(uint4*)&Al[ar][ak] = ql;
            split_tf32(v1.x, qh.x, ql.x); split_tf32(v1.y, qh.y, ql.y);
            split_tf32(v1.z, qh.z, ql.z); split_tf32(v1.w, qh.w, ql.w);
            *(uint4*)&Ah[ar][ak + 4] = qh; *(uint4*)&Al[ar][ak + 4] = ql;
        }
        if (TRANSB) {   // B [N,K] -> Bs[k][n]
            int br = tid >> 2, bk = (tid & 3) * 4;
            const float* bp = B + (size_t)(n0 + br) * K + k0 + bk;
            float4 v = *(const float4*)bp;
            u32 h, l;
            split_tf32(v.x, h, l); Bh[bk + 0][br] = h; Bl[bk + 0][br] = l;
            split_tf32(v.y, h, l); Bh[bk + 1][br] = h; Bl[bk + 1][br] = l;
            split_tf32(v.z, h, l); Bh[bk + 2][br] = h; Bl[bk + 2][br] = l;
            split_tf32(v.w, h, l); Bh[bk + 3][br] = h; Bl[bk + 3][br] = l;
        } else {        // B [K,N]
            int bk = tid >> 4, bn = (tid & 15) * 4;
            const float* bp = B + (size_t)(k0 + bk) * N + n0 + bn;
            float4 v = *(const float4*)bp;
            uint4 qh, ql;
            split_tf32(v.x, qh.x, ql.x); split_tf32(v.y, qh.y, ql.y);
            split_tf32(v.z, qh.z, ql.z); split_tf32(v.w, qh.w, ql.w);
            *(uint4*)&Bh[bk][bn] = qh; *(uint4*)&Bl[bk][bn] = ql;
        }
        __syncthreads();
#pragma unroll
        for (int ks = 0; ks < 2; ks++) {
            const int kb = ks * 8;
            u32 afh[2][4], afl[2][4], bfh[4][2], bfl[4][2];
#pragma unroll
            for (int mt = 0; mt < 2; mt++) {
                int r = wm + mt * 16 + g;
                afh[mt][0] = Ah[r][kb + tig];
                afh[mt][1] = Ah[r + 8][kb + tig];
                afh[mt][2] = Ah[r][kb + tig + 4];
                afh[mt][3] = Ah[r + 8][kb + tig + 4];
                afl[mt][0] = Al[r][kb + tig];
                afl[mt][1] = Al[r + 8][kb + tig];
                afl[mt][2] = Al[r][kb + tig + 4];
                afl[mt][3] = Al[r + 8][kb + tig + 4];
            }
#pragma unroll
            for (int nt = 0; nt < 4; nt++) {
                bfh[nt][0] = Bh[kb + tig][wn + nt * 8 + g];
                bfh[nt][1] = Bh[kb + tig + 4][wn + nt * 8 + g];
                bfl[nt][0] = Bl[kb + tig][wn + nt * 8 + g];
                bfl[nt][1] = Bl[kb + tig + 4][wn + nt * 8 + g];
            }
#pragma unroll
            for (int mt = 0; mt < 2; mt++)
#pragma unroll
                for (int nt = 0; nt < 4; nt++) {
                    mma8(acc[mt][nt], afl[mt], bfh[nt]);   // small terms first
                    mma8(acc[mt][nt], afh[mt], bfl[nt]);
                    mma8(acc[mt][nt], afh[mt], bfh[nt]);
                }
        }
        __syncthreads();
    }
#pragma unroll
    for (int mt = 0; mt < 2; mt++) {
#pragma unroll
        for (int nt = 0; nt < 4; nt++) {
            int c = n0 + wn + nt * 8 + 2 * tig;
#pragma unroll
            for (int h = 0; h < 2; h++) {
                int r = m0 + wm + mt * 16 + g + h * 8;
                float2 v = make_float2(acc[mt][nt][h * 2], acc[mt][nt][h * 2 + 1]);
                if (bi) { v.x += bi[c]; v.y += bi[c + 1]; }
                float2* cp = (float2*)&C[(size_t)r * N + c];
                if (addC) { float2 o = *cp; v.x += o.x; v.y += o.y; }
                if (RELU) { v.x = fmaxf(v.x, 0.f); v.y = fmaxf(v.y, 0.f); }
                *cp = v;
            }
        }
    }
}

// ---------------- graph kernels ----------------
__global__ void count_kernel(const int* __restrict__ ei, const int* __restrict__ et,
                             float* __restrict__ cnt) {
    int e = blockIdx.x * 256 + threadIdx.x;
    if (e < EE) atomicAdd(&cnt[ei[EE + e] * RRE + et[e]], 1.0f);
}

__global__ void rgcn_scatter_kernel(const float* __restrict__ hrel, const int* __restrict__ ei,
                                    const int* __restrict__ et, const float* __restrict__ cnt,
                                    float* __restrict__ out1) {
    int e = blockIdx.x * 4 + (threadIdx.x >> 6);
    int lane = threadIdx.x & 63;
    int src = ei[e], dst = ei[EE + e], r = et[e];
    float inv = 1.0f / fmaxf(cnt[dst * RRE + r], 1.0f);
    float4 v = ((const float4*)(hrel + ((size_t)r * NN + src) * HIDN))[lane];
    float* o = out1 + (size_t)dst * HIDN + lane * 4;
    atomicAdd(o + 0, v.x * inv);
    atomicAdd(o + 1, v.y * inv);
    atomicAdd(o + 2, v.z * inv);
    atomicAdd(o + 3, v.w * inv);
}

__global__ void gconv_scatter_kernel(const float* __restrict__ out1, const int* __restrict__ ei,
                                     float* __restrict__ agg) {
    int e = blockIdx.x * 4 + (threadIdx.x >> 6);
    int lane = threadIdx.x & 63;
    int src = ei[e], dst = ei[EE + e];
    float4 v = ((const float4*)(out1 + (size_t)src * HIDN))[lane];
    float* o = agg + (size_t)dst * HIDN + lane * 4;
    atomicAdd(o + 0, v.x);
    atomicAdd(o + 1, v.y);
    atomicAdd(o + 2, v.z);
    atomicAdd(o + 3, v.w);
}

__global__ void concat_kernel(const float* __restrict__ feat, const float* __restrict__ out2,
                              float* __restrict__ x0) {
    int n = blockIdx.x;
    int b = n >> 7, s = n & 127;
    float* dstrow = x0 + (size_t)(s * BBS + b) * DHH;
    for (int d = threadIdx.x; d < DHH; d += 256)
        dstrow[d] = (d < FIN) ? feat[(size_t)n * FIN + d] : out2[(size_t)n * HIDN + (d - FIN)];
}

// ---------------- persistent BiLSTM layer ----------------
#define NBLK 256
#define SMEM_LSTM ((12 * 768 + 32 * 33) * 8)   // Wif+Wgo (6x768 u64 each) + Hd

__device__ __forceinline__ void gbar(unsigned phase) {
    __syncthreads();
    if (threadIdx.x == 0) {
        __threadfence();
        unsigned a = atomicAdd(&g_bar[0], 1u);
        if (a == NBLK - 1u) {
            g_bar[0] = 0u;
            __threadfence();
            atomicExch(&g_bar[1], phase + 1u);
        } else {
            while (atomicAdd(&g_bar[1], 0u) <= phase) __nanosleep(64);
        }
        __threadfence();
    }
    __syncthreads();
}

// grid = 256 blocks (d = bx>>7, j0 = (bx&127)*6), 192 threads.
__global__ __launch_bounds__(192) void lstm_layer_kernel(
    const float* __restrict__ Whh, const float* __restrict__ gpre,
    float* __restrict__ state, float* __restrict__ hout)
{
    extern __shared__ u64 dsm[];
    u64 (*Wif)[768] = (u64(*)[768])dsm;
    u64 (*Wgo)[768] = (u64(*)[768])(dsm + 6 * 768);
    u64 (*Hd)[33]   = (u64(*)[33])(dsm + 12 * 768);

    const int bx = blockIdx.x;
    const int d = bx >> 7;
    const int j0 = (bx & 127) * 6;
    const int tid = threadIdx.x;
    const int jj = tid >> 5, b = tid & 31;
    const int j = j0 + jj;
    const float* Wb = Whh + (size_t)d * GG4 * DHH;

    for (int jr = 0; jr < 6; jr++) {
        int jg = j0 + jr;
        for (int k = tid; k < DHH; k += 192) {
            Wif[jr][k] = fpack2(Wb[(size_t)jg * DHH + k],
                                Wb[(size_t)(DHH + jg) * DHH + k]);
            Wgo[jr][k] = fpack2(Wb[(size_t)(2 * DHH + jg) * DHH + k],
                                Wb[(size_t)(3 * DHH + jg) * DHH + k]);
        }
    }
    __syncthreads();

    float creg = 0.0f;
    for (int t = 0; t < SSEQ; t++) {
        const int tdir = (d == 0) ? t : (SSEQ - 1 - t);
        const float* hin = state + (t & 1) * (2 * BBS * DHH) + d * (BBS * DHH);
        float* hOut = state + ((t + 1) & 1) * (2 * BBS * DHH) + d * (BBS * DHH);

        u64 pIF = 0ull, pGO = 0ull;
        for (int k0 = 0; k0 < DHH; k0 += 32) {
            for (int q = tid; q < 256; q += 192) {
                int hr = q >> 3, hk = (q & 7) * 4;
                float4 v = *(const float4*)(hin + hr * DHH + k0 + hk);
                Hd[hr][hk + 0] = fpack2(v.x, v.x);
                Hd[hr][hk + 1] = fpack2(v.y, v.y);
                Hd[hr][hk + 2] = fpack2(v.z, v.z);
                Hd[hr][hk + 3] = fpack2(v.w, v.w);
            }
            __syncthreads();
#pragma unroll
            for (int kk = 0; kk < 32; kk++) {
                u64 hp = Hd[b][kk];
                pIF = ffma2(Wif[jj][k0 + kk], hp, pIF);
                pGO = ffma2(Wgo[jj][k0 + kk], hp, pGO);
            }
            __syncthreads();
        }
        float2 vif = funpack2(pIF);
        float2 vgo = funpack2(pGO);
        int row = tdir * BBS + b;
        const float* gp = gpre + ((size_t)d * NN + row) * GG4;
        float gi = vif.x + gp[j];
        float gf = vif.y + gp[DHH + j];
        float gg = vgo.x + gp[2 * DHH + j];
        float go = vgo.y + gp[3 * DHH + j];
        creg = sigf(gf) * creg + sigf(gi) * tanhf(gg);
        float h = sigf(go) * tanhf(creg);
        hOut[b * DHH + j] = h;
        hout[(size_t)row * DD2 + d * DHH + j] = h;
        gbar((unsigned)t);
    }
}

// ---------------- attention ----------------
__global__ __launch_bounds__(256) void attention_kernel(
    const float* __restrict__ M, const float* __restrict__ X,
    const float* __restrict__ umask, float* __restrict__ att)
{
    const int b = blockIdx.y;
    const int t0 = blockIdx.x * 16;
    const int tid = threadIdx.x;
    const int ti = tid >> 4, si = tid & 15;

    __shared__ float Ms[128][33];
    __shared__ float Xs[16][33];
    __shared__ float Aa[16][129];
    __shared__ float um[128];
    if (tid < 128) um[tid] = umask[b * SSEQ + tid];
    __syncthreads();

    float acc[8];
#pragma unroll
    for (int u = 0; u < 8; u++) acc[u] = 0.0f;

    for (int k0 = 0; k0 < DD2; k0 += 32) {
        {
            int s = tid >> 1;
            float u = um[s];
            const float* mrow = M + ((size_t)(s * BBS + b)) * DD2 + k0;
#pragma unroll
            for (int i = 0; i < 4; i++) {
                int c = (tid & 1) * 16 + i * 4;
                float4 v = *(const float4*)(mrow + c);
                Ms[s][c] = v.x * u; Ms[s][c + 1] = v.y * u;
                Ms[s][c + 2] = v.z * u; Ms[s][c + 3] = v.w * u;
            }
        }
        if (tid < 128) {
            int r = tid >> 3, c = (tid & 7) * 4;
            float4 v = *(const float4*)(X + ((size_t)((t0 + r) * BBS + b)) * DD2 + k0 + c);
            Xs[r][c] = v.x; Xs[r][c + 1] = v.y; Xs[r][c + 2] = v.z; Xs[r][c + 3] = v.w;
        }
        __syncthreads();
#pragma unroll
        for (int kk = 0; kk < 32; kk++) {
            float xv = Xs[ti][kk];
#pragma unroll
            for (int u = 0; u < 8; u++) acc[u] += xv * Ms[si * 8 + u][kk];
        }
        __syncthreads();
    }

#pragma unroll
    for (int u = 0; u < 8; u++) acc[u] = tanhf(acc[u] * um[si * 8 + u]);
    float mx = -1e30f;
#pragma unroll
    for (int u = 0; u < 8; u++) mx = fmaxf(mx, acc[u]);
    for (int o = 8; o >= 1; o >>= 1) mx = fmaxf(mx, __shfl_xor_sync(0xffffffffu, mx, o, 16));
    float a[8]; float s2 = 0.0f;
#pragma unroll
    for (int u = 0; u < 8; u++) {
        a[u] = expf(acc[u] - mx) * um[si * 8 + u];
        s2 += a[u];
    }
    for (int o = 8; o >= 1; o >>= 1) s2 += __shfl_xor_sync(0xffffffffu, s2, o, 16);
    float inv = 1.0f / s2;
#pragma unroll
    for (int u = 0; u < 8; u++) Aa[ti][si * 8 + u] = a[u] * inv;
    __syncthreads();

    for (int d0 = 0; d0 < DD2; d0 += 32) {
        {
            int s = tid >> 1;
            const float* mrow = M + ((size_t)(s * BBS + b)) * DD2 + d0;
#pragma unroll
            for (int i = 0; i < 4; i++) {
                int c = (tid & 1) * 16 + i * 4;
                float4 v = *(const float4*)(mrow + c);
                Ms[s][c] = v.x; Ms[s][c + 1] = v.y; Ms[s][c + 2] = v.z; Ms[s][c + 3] = v.w;
            }
        }
        __syncthreads();
        int dloc = (tid & 15) * 2;
        float r0 = 0.f, r1 = 0.f;
#pragma unroll 8
        for (int s = 0; s < 128; s++) {
            float al = Aa[ti][s];
            r0 += al * Ms[s][dloc];
            r1 += al * Ms[s][dloc + 1];
        }
        float* orow = att + ((size_t)((t0 + ti) * BBS + b)) * DD2 + d0 + dloc;
        orow[0] = r0; orow[1] = r1;
        __syncthreads();
    }
}

// ---------------- launch ----------------
extern "C" void kernel_launch(void* const* d_in, const int* in_sizes, int n_in,
                              void* d_out, int out_size) {
    const float* feat   = (const float*)d_in[0];
    const int*   ei     = (const int*)d_in[1];
    const int*   et     = (const int*)d_in[2];
    const float* umask  = (const float*)d_in[4];
    const float* Wrel   = (const float*)d_in[5];
    const float* Wroot  = (const float*)d_in[6];
    const float* rb     = (const float*)d_in[7];
    const float* gcWrel = (const float*)d_in[8];
    const float* gcWroot= (const float*)d_in[9];
    const float* gcb    = (const float*)d_in[10];
    const float* Wih0   = (const float*)d_in[11];
    const float* Whh0   = (const float*)d_in[12];
    const float* b0     = (const float*)d_in[13];
    const float* Wih1   = (const float*)d_in[14];
    const float* Whh1   = (const float*)d_in[15];
    const float* b1     = (const float*)d_in[16];
    const float* mattW  = (const float*)d_in[17];
    const float* mattb  = (const float*)d_in[18];
    const float* linW   = (const float*)d_in[19];
    const float* linb   = (const float*)d_in[20];
    float* out = (float*)d_out;

    float *hrel, *out1, *cnt, *agg, *out2, *x0, *g0, *h0, *g1, *Mb, *st, *Xb, *attb, *barp;
    cudaGetSymbolAddress((void**)&hrel, g_hrel);
    cudaGetSymbolAddress((void**)&out1, g_out1);
    cudaGetSymbolAddress((void**)&cnt,  g_cnt);
    cudaGetSymbolAddress((void**)&agg,  g_agg);
    cudaGetSymbolAddress((void**)&out2, g_out2);
    cudaGetSymbolAddress((void**)&x0,   g_x0);
    cudaGetSymbolAddress((void**)&g0,   g_g0);
    cudaGetSymbolAddress((void**)&h0,   g_h0);
    cudaGetSymbolAddress((void**)&g1,   g_g1);
    cudaGetSymbolAddress((void**)&Mb,   g_M);
    cudaGetSymbolAddress((void**)&st,   g_st);
    cudaGetSymbolAddress((void**)&Xb,   g_X);
    cudaGetSymbolAddress((void**)&attb, g_att);
    cudaGetSymbolAddress((void**)&barp, g_bar);

    cudaFuncSetAttribute(lstm_layer_kernel,
                         cudaFuncAttributeMaxDynamicSharedMemorySize, SMEM_LSTM);

    // --- graph stage ---
    fill_zero_kernel<<<(NN * RRE + 255) / 256, 256>>>(cnt, NN * RRE);
    fill_zero_kernel<<<(NN * HIDN + 255) / 256, 256>>>(agg, NN * HIDN);
    count_kernel<<<EE / 256, 256>>>(ei, et, cnt);
    tgemm_kernel<false, false><<<dim3(4, 32, 1), 256>>>(feat, Wroot, rb, out1,
        NN, HIDN, FIN, 0, 0, 0, 0, 0);
    tgemm_kernel<false, false><<<dim3(4, 32, RRE), 256>>>(feat, Wrel, nullptr, hrel,
        NN, HIDN, FIN, 0, (size_t)FIN * HIDN, 0, (size_t)NN * HIDN, 0);
    rgcn_scatter_kernel<<<EE / 4, 256>>>(hrel, ei, et, cnt, out1);
    gconv_scatter_kernel<<<EE / 4, 256>>>(out1, ei, agg);
    tgemm_kernel<false, false><<<dim3(4, 32, 1), 256>>>(agg, gcWrel, gcb, out2,
        NN, HIDN, HIDN, 0, 0, 0, 0, 0);
    tgemm_kernel<false, false><<<dim3(4, 32, 1), 256>>>(out1, gcWroot, nullptr, out2,
        NN, HIDN, HIDN, 0, 0, 0, 0, 1);
    concat_kernel<<<NN, 256>>>(feat, out2, x0);

    // --- BiLSTM layer 0 ---
    tgemm_kernel<true, false><<<dim3(48, 32, 2), 256>>>(x0, Wih0, b0, g0,
        NN, GG4, DHH, 0, (size_t)GG4 * DHH, GG4, (size_t)NN * GG4, 0);
    fill_zero_kernel<<<(2 * 2 * BBS * DHH + 255) / 256, 256>>>(st, 2 * 2 * BBS * DHH);
    fill_zero_kernel<<<1, 256>>>(barp, 2);
    lstm_layer_kernel<<<NBLK, 192, SMEM_LSTM>>>(Whh0, g0, st, h0);

    // --- BiLSTM layer 1 ---
    tgemm_kernel<true, false><<<dim3(48, 32, 2), 256>>>(h0, Wih1, b1, g1,
        NN, GG4, DD2, 0, (size_t)GG4 * DD2, GG4, (size_t)NN * GG4, 0);
    fill_zero_kernel<<<(2 * 2 * BBS * DHH + 255) / 256, 256>>>(st, 2 * 2 * BBS * DHH);
    fill_zero_kernel<<<1, 256>>>(barp, 2);
    lstm_layer_kernel<<<NBLK, 192, SMEM_LSTM>>>(Whh1, g1, st, Mb);

    // --- attention + output ---
    tgemm_kernel<true, false><<<dim3(24, 32, 1), 256>>>(Mb, mattW, mattb, Xb,
        NN, DD2, DD2, 0, 0, 0, 0, 0);
    attention_kernel<<<dim3(8, 32), 256>>>(Mb, Xb, umask, attb);
    tgemm_kernel<true, true><<<dim3(12, 32, 1), 256>>>(attb, linW, linb, out,
        NN, DHH, DD2, 0, 0, 0, 0, 0);
}

// round 9
// speedup vs baseline: 1.5406x; 1.2495x over previous
#include <cuda_runtime.h>
#include <math.h>

#define NN    4096
#define FIN   512
#define HIDN  256
#define RRE   16
#define EE    65536
#define BBS   32
#define SSEQ  128
#define DHH   768
#define DD2   1536
#define GG4   3072

typedef unsigned long long u64;
typedef unsigned int u32;

// ---------------- tf32 helpers ----------------
__device__ __forceinline__ u32 cvtf(float x) {
    u32 r; asm("cvt.rna.tf32.f32 %0, %1;" : "=r"(r) : "f"(x)); return r;
}
__device__ __forceinline__ void split_tf32(float x, u32& hi, u32& lo) {
    hi = cvtf(x);
    lo = cvtf(x - __uint_as_float(hi));
}
__device__ __forceinline__ void mma8(float* d, const u32* a, const u32* b) {
    asm("mma.sync.aligned.m16n8k8.row.col.f32.tf32.tf32.f32 "
        "{%0,%1,%2,%3}, {%4,%5,%6,%7}, {%8,%9}, {%0,%1,%2,%3};"
        : "+f"(d[0]), "+f"(d[1]), "+f"(d[2]), "+f"(d[3])
        : "r"(a[0]), "r"(a[1]), "r"(a[2]), "r"(a[3]), "r"(b[0]), "r"(b[1]));
}

// ---------------- device scratch ----------------
__device__ float g_hrel[(size_t)RRE * NN * HIDN];
__device__ float g_out1[(size_t)NN * HIDN];
__device__ float g_cnt[(size_t)NN * RRE];
__device__ float g_agg[(size_t)NN * HIDN];
__device__ float g_out2[(size_t)NN * HIDN];
__device__ float g_x0[(size_t)NN * DHH];
__device__ float g_g0[(size_t)2 * NN * GG4];
__device__ float g_h0[(size_t)NN * DD2];
__device__ float g_g1[(size_t)2 * NN * GG4];
__device__ float g_M[(size_t)NN * DD2];
__device__ float g_X[(size_t)NN * DD2];
__device__ float g_att[(size_t)NN * DD2];
__device__ u64 g_ws[(size_t)2 * GG4 * DHH];     // pre-split Whh (hi in low 32b)
__device__ u64 g_hs[(size_t)2 * 2 * BBS * DHH]; // h state split [parity][dir][b][k]
__device__ unsigned g_bar[2];                   // cnt, gen

__global__ void fill_zero_kernel(float* p, int n) {
    int i = blockIdx.x * 256 + threadIdx.x;
    if (i < n) p[i] = 0.0f;
}

__device__ __forceinline__ float sigf(float x) { return 1.0f / (1.0f + expf(-x)); }

// ---------------- 3xTF32 tensor-core GEMM ----------------
template<bool TRANSB, bool RELU>
__global__ __launch_bounds__(256) void tgemm_kernel(
    const float* __restrict__ A, const float* __restrict__ B,
    const float* __restrict__ bias, float* __restrict__ C,
    int M, int N, int K,
    size_t sA, size_t sB, size_t sBias, size_t sC, int addC)
{
    A += (size_t)blockIdx.z * sA;
    B += (size_t)blockIdx.z * sB;
    C += (size_t)blockIdx.z * sC;
    const float* bi = bias ? bias + (size_t)blockIdx.z * sBias : (const float*)0;

    __shared__ u32 Ah[128][20];
    __shared__ u32 Al[128][20];
    __shared__ u32 Bh[16][76];
    __shared__ u32 Bl[16][76];
    const int m0 = blockIdx.y * 128, n0 = blockIdx.x * 64;
    const int tid = threadIdx.x;
    const int lane = tid & 31, wid = tid >> 5;
    const int wm = (wid & 3) * 32, wn = (wid >> 2) * 32;
    const int g = lane >> 2, tig = lane & 3;

    float acc[2][4][4];
#pragma unroll
    for (int mt = 0; mt < 2; mt++)
#pragma unroll
        for (int nt = 0; nt < 4; nt++)
#pragma unroll
            for (int q = 0; q < 4; q++) acc[mt][nt][q] = 0.0f;

    for (int k0 = 0; k0 < K; k0 += 16) {
        {
            int ar = tid >> 1, ak = (tid & 1) * 8;
            const float* ap = A + (size_t)(m0 + ar) * K + k0 + ak;
            float4 v0 = *(const float4*)ap, v1 = *(const float4*)(ap + 4);
            uint4 qh, ql;
            split_tf32(v0.x, qh.x, ql.x); split_tf32(v0.y, qh.y, ql.y);
            split_tf32(v0.z, qh.z, ql.z); split_tf32(v0.w, qh.w, ql.w);
            *(uint4*)&Ah[ar][ak] = qh; *(uint4*)&Al[ar][ak] = ql;
            split_tf32(v1.x, qh.x, ql.x); split_tf32(v1.y, qh.y, ql.y);
            split_tf32(v1.z, qh.z, ql.z); split_tf32(v1.w, qh.w, ql.w);
            *(uint4*)&Ah[ar][ak + 4] = qh; *(uint4*)&Al[ar][ak + 4] = ql;
        }
        if (TRANSB) {
            int br = tid >> 2, bk = (tid & 3) * 4;
            const float* bp = B + (size_t)(n0 + br) * K + k0 + bk;
            float4 v = *(const float4*)bp;
            u32 h, l;
            split_tf32(v.x, h, l); Bh[bk + 0][br] = h; Bl[bk + 0][br] = l;
            split_tf32(v.y, h, l); Bh[bk + 1][br] = h; Bl[bk + 1][br] = l;
            split_tf32(v.z, h, l); Bh[bk + 2][br] = h; Bl[bk + 2][br] = l;
            split_tf32(v.w, h, l); Bh[bk + 3][br] = h; Bl[bk + 3][br] = l;
        } else {
            int bk = tid >> 4, bn = (tid & 15) * 4;
            const float* bp = B + (size_t)(k0 + bk) * N + n0 + bn;
            float4 v = *(const float4*)bp;
            uint4 qh, ql;
            split_tf32(v.x, qh.x, ql.x); split_tf32(v.y, qh.y, ql.y);
            split_tf32(v.z, qh.z, ql.z); split_tf32(v.w, qh.w, ql.w);
            *(uint4*)&Bh[bk][bn] = qh; *(uint4*)&Bl[bk][bn] = ql;
        }
        __syncthreads();
#pragma unroll
        for (int ks = 0; ks < 2; ks++) {
            const int kb = ks * 8;
            u32 afh[2][4], afl[2][4], bfh[4][2], bfl[4][2];
#pragma unroll
            for (int mt = 0; mt < 2; mt++) {
                int r = wm + mt * 16 + g;
                afh[mt][0] = Ah[r][kb + tig];
                afh[mt][1] = Ah[r + 8][kb + tig];
                afh[mt][2] = Ah[r][kb + tig + 4];
                afh[mt][3] = Ah[r + 8][kb + tig + 4];
                afl[mt][0] = Al[r][kb + tig];
                afl[mt][1] = Al[r + 8][kb + tig];
                afl[mt][2] = Al[r][kb + tig + 4];
                afl[mt][3] = Al[r + 8][kb + tig + 4];
            }
#pragma unroll
            for (int nt = 0; nt < 4; nt++) {
                bfh[nt][0] = Bh[kb + tig][wn + nt * 8 + g];
                bfh[nt][1] = Bh[kb + tig + 4][wn + nt * 8 + g];
                bfl[nt][0] = Bl[kb + tig][wn + nt * 8 + g];
                bfl[nt][1] = Bl[kb + tig + 4][wn + nt * 8 + g];
            }
#pragma unroll
            for (int mt = 0; mt < 2; mt++)
#pragma unroll
                for (int nt = 0; nt < 4; nt++) {
                    mma8(acc[mt][nt], afl[mt], bfh[nt]);
                    mma8(acc[mt][nt], afh[mt], bfl[nt]);
                    mma8(acc[mt][nt], afh[mt], bfh[nt]);
                }
        }
        __syncthreads();
    }
#pragma unroll
    for (int mt = 0; mt < 2; mt++) {
#pragma unroll
        for (int nt = 0; nt < 4; nt++) {
            int c = n0 + wn + nt * 8 + 2 * tig;
#pragma unroll
            for (int h = 0; h < 2; h++) {
                int r = m0 + wm + mt * 16 + g + h * 8;
                float2 v = make_float2(acc[mt][nt][h * 2], acc[mt][nt][h * 2 + 1]);
                if (bi) { v.x += bi[c]; v.y += bi[c + 1]; }
                float2* cp = (float2*)&C[(size_t)r * N + c];
                if (addC) { float2 o = *cp; v.x += o.x; v.y += o.y; }
                if (RELU) { v.x = fmaxf(v.x, 0.f); v.y = fmaxf(v.y, 0.f); }
                *cp = v;
            }
        }
    }
}

// ---------------- graph kernels ----------------
__global__ void count_kernel(const int* __restrict__ ei, const int* __restrict__ et,
                             float* __restrict__ cnt) {
    int e = blockIdx.x * 256 + threadIdx.x;
    if (e < EE) atomicAdd(&cnt[ei[EE + e] * RRE + et[e]], 1.0f);
}

__global__ void rgcn_scatter_kernel(const float* __restrict__ hrel, const int* __restrict__ ei,
                                    const int* __restrict__ et, const float* __restrict__ cnt,
                                    float* __restrict__ out1) {
    int e = blockIdx.x * 4 + (threadIdx.x >> 6);
    int lane = threadIdx.x & 63;
    int src = ei[e], dst = ei[EE + e], r = et[e];
    float inv = 1.0f / fmaxf(cnt[dst * RRE + r], 1.0f);
    float4 v = ((const float4*)(hrel + ((size_t)r * NN + src) * HIDN))[lane];
    float* o = out1 + (size_t)dst * HIDN + lane * 4;
    atomicAdd(o + 0, v.x * inv);
    atomicAdd(o + 1, v.y * inv);
    atomicAdd(o + 2, v.z * inv);
    atomicAdd(o + 3, v.w * inv);
}

__global__ void gconv_scatter_kernel(const float* __restrict__ out1, const int* __restrict__ ei,
                                     float* __restrict__ agg) {
    int e = blockIdx.x * 4 + (threadIdx.x >> 6);
    int lane = threadIdx.x & 63;
    int src = ei[e], dst = ei[EE + e];
    float4 v = ((const float4*)(out1 + (size_t)src * HIDN))[lane];
    float* o = agg + (size_t)dst * HIDN + lane * 4;
    atomicAdd(o + 0, v.x);
    atomicAdd(o + 1, v.y);
    atomicAdd(o + 2, v.z);
    atomicAdd(o + 3, v.w);
}

__global__ void concat_kernel(const float* __restrict__ feat, const float* __restrict__ out2,
                              float* __restrict__ x0) {
    int n = blockIdx.x;
    int b = n >> 7, s = n & 127;
    float* dstrow = x0 + (size_t)(s * BBS + b) * DHH;
    for (int d = threadIdx.x; d < DHH; d += 256)
        dstrow[d] = (d < FIN) ? feat[(size_t)n * FIN + d] : out2[(size_t)n * HIDN + (d - FIN)];
}

// ---------------- persistent tensor-core BiLSTM ----------------
#define NBLK 96
#define SMEM_TLSTM ((8 * 32 * 68 + 32 * 68) * 4)

__device__ __forceinline__ void gbar(unsigned phase) {
    __syncthreads();
    if (threadIdx.x == 0) {
        __threadfence();
        unsigned a = atomicAdd(&g_bar[0], 1u);
        if (a == NBLK - 1u) {
            g_bar[0] = 0u;
            __threadfence();
            atomicExch(&g_bar[1], phase + 1u);
        } else {
            while (atomicAdd(&g_bar[1], 0u) <= phase) __nanosleep(64);
        }
        __threadfence();
    }
    __syncthreads();
}

// pre-split Whh into packed (tf32 hi | lo<<32)
__global__ void wsplit_kernel(const float* __restrict__ W, u64* __restrict__ Ws, int n) {
    int i = blockIdx.x * 256 + threadIdx.x;
    if (i < n) {
        u32 h, l; split_tf32(W[i], h, l);
        Ws[i] = ((u64)l << 32) | h;
    }
}

// grid = 96 (dir = bx&1, jblk = bx>>1 of 48), 256 threads (8 warps K-split).
// Block computes gates[32 b][64 cols] = h @ W^T for its 16 hidden units x 4 gates.
__global__ __launch_bounds__(256) void lstm_tc_kernel(
    const u64* __restrict__ Ws, const float* __restrict__ gpre,
    u64* __restrict__ hs, float* __restrict__ hout)
{
    extern __shared__ float sm[];
    float* part = sm;                  // [8][32][68]
    float* gsum = sm + 8 * 32 * 68;    // [32][68]

    const int bx = blockIdx.x;
    const int dir = bx & 1;
    const int j0 = (bx >> 1) * 16;
    const int tid = threadIdx.x;
    const int w = tid >> 5, lane = tid & 31;
    const int g = lane >> 2, tig = lane & 3;
    const u64* Wd = Ws + (size_t)dir * GG4 * DHH;

    float cst[2] = {0.0f, 0.0f};

    for (int t = 0; t < SSEQ; t++) {
        const u64* hin = hs + ((size_t)(t & 1) * 2 + dir) * (BBS * DHH);
        u64* hOutp     = hs + ((size_t)((t + 1) & 1) * 2 + dir) * (BBS * DHH);

        float acc[2][8][4];
#pragma unroll
        for (int mt = 0; mt < 2; mt++)
#pragma unroll
            for (int nt = 0; nt < 8; nt++)
#pragma unroll
                for (int q = 0; q < 4; q++) acc[mt][nt][q] = 0.0f;

        for (int s = 0; s < 12; s++) {
            const int k0 = w * 96 + s * 8;
            u32 ah[2][4], al[2][4];
#pragma unroll
            for (int mt = 0; mt < 2; mt++) {
                int r0 = mt * 16 + g;
                u64 v0 = hin[r0 * DHH + k0 + tig];
                u64 v1 = hin[(r0 + 8) * DHH + k0 + tig];
                u64 v2 = hin[r0 * DHH + k0 + tig + 4];
                u64 v3 = hin[(r0 + 8) * DHH + k0 + tig + 4];
                ah[mt][0] = (u32)v0; al[mt][0] = (u32)(v0 >> 32);
                ah[mt][1] = (u32)v1; al[mt][1] = (u32)(v1 >> 32);
                ah[mt][2] = (u32)v2; al[mt][2] = (u32)(v2 >> 32);
                ah[mt][3] = (u32)v3; al[mt][3] = (u32)(v3 >> 32);
            }
#pragma unroll
            for (int nt = 0; nt < 8; nt++) {
                int n = (nt >> 1) * DHH + j0 + (nt & 1) * 8 + g;
                u64 w0 = Wd[(size_t)n * DHH + k0 + tig];
                u64 w1 = Wd[(size_t)n * DHH + k0 + tig + 4];
                u32 bh[2] = {(u32)w0, (u32)w1};
                u32 bl[2] = {(u32)(w0 >> 32), (u32)(w1 >> 32)};
#pragma unroll
                for (int mt = 0; mt < 2; mt++) {
                    mma8(acc[mt][nt], al[mt], bh);
                    mma8(acc[mt][nt], ah[mt], bl);
                    mma8(acc[mt][nt], ah[mt], bh);
                }
            }
        }
        // store K-partials
#pragma unroll
        for (int mt = 0; mt < 2; mt++)
#pragma unroll
            for (int nt = 0; nt < 8; nt++) {
                int b0 = mt * 16 + g, c = nt * 8 + 2 * tig;
                float* p0 = &part[(w * 32 + b0) * 68 + c];
                p0[0] = acc[mt][nt][0]; p0[1] = acc[mt][nt][1];
                float* p1 = &part[(w * 32 + b0 + 8) * 68 + c];
                p1[0] = acc[mt][nt][2]; p1[1] = acc[mt][nt][3];
            }
        __syncthreads();
        // reduce over 8 warps
        {
            int b = tid >> 3, cb = (tid & 7) * 8;
            float4 r0 = make_float4(0, 0, 0, 0), r1 = make_float4(0, 0, 0, 0);
#pragma unroll
            for (int ww = 0; ww < 8; ww++) {
                const float* p = &part[(ww * 32 + b) * 68 + cb];
                float4 a = *(const float4*)p;
                float4 b4 = *(const float4*)(p + 4);
                r0.x += a.x; r0.y += a.y; r0.z += a.z; r0.w += a.w;
                r1.x += b4.x; r1.y += b4.y; r1.z += b4.z; r1.w += b4.w;
            }
            *(float4*)&gsum[b * 68 + cb] = r0;
            *(float4*)&gsum[b * 68 + cb + 4] = r1;
        }
        __syncthreads();
        // gate nonlinearity + state update (512 (b,j) pairs, 2 per thread)
        const int tdir = dir ? (SSEQ - 1 - t) : t;
#pragma unroll
        for (int u = 0; u < 2; u++) {
            int pr = tid + u * 256;
            int b = pr >> 4, jl = pr & 15;
            int j = j0 + jl;
            int row = tdir * BBS + b;
            const float* gp = gpre + ((size_t)dir * NN + row) * GG4;
            float gi = gsum[b * 68 + jl]       + gp[j];
            float gf = gsum[b * 68 + 16 + jl]  + gp[DHH + j];
            float gg = gsum[b * 68 + 32 + jl]  + gp[2 * DHH + j];
            float go = gsum[b * 68 + 48 + jl]  + gp[3 * DHH + j];
            float c = sigf(gf) * cst[u] + sigf(gi) * tanhf(gg);
            cst[u] = c;
            float h = sigf(go) * tanhf(c);
            hout[(size_t)row * DD2 + dir * DHH + j] = h;
            u32 hh, hl; split_tf32(h, hh, hl);
            hOutp[b * DHH + j] = ((u64)hl << 32) | hh;
        }
        gbar((unsigned)t);
    }
}

// ---------------- attention ----------------
__global__ __launch_bounds__(256) void attention_kernel(
    const float* __restrict__ M, const float* __restrict__ X,
    const float* __restrict__ umask, float* __restrict__ att)
{
    const int b = blockIdx.y;
    const int t0 = blockIdx.x * 16;
    const int tid = threadIdx.x;
    const int ti = tid >> 4, si = tid & 15;

    __shared__ float Ms[128][33];
    __shared__ float Xs[16][33];
    __shared__ float Aa[16][129];
    __shared__ float um[128];
    if (tid < 128) um[tid] = umask[b * SSEQ + tid];
    __syncthreads();

    float acc[8];
#pragma unroll
    for (int u = 0; u < 8; u++) acc[u] = 0.0f;

    for (int k0 = 0; k0 < DD2; k0 += 32) {
        {
            int s = tid >> 1;
            float u = um[s];
            const float* mrow = M + ((size_t)(s * BBS + b)) * DD2 + k0;
#pragma unroll
            for (int i = 0; i < 4; i++) {
                int c = (tid & 1) * 16 + i * 4;
                float4 v = *(const float4*)(mrow + c);
                Ms[s][c] = v.x * u; Ms[s][c + 1] = v.y * u;
                Ms[s][c + 2] = v.z * u; Ms[s][c + 3] = v.w * u;
            }
        }
        if (tid < 128) {
            int r = tid >> 3, c = (tid & 7) * 4;
            float4 v = *(const float4*)(X + ((size_t)((t0 + r) * BBS + b)) * DD2 + k0 + c);
            Xs[r][c] = v.x; Xs[r][c + 1] = v.y; Xs[r][c + 2] = v.z; Xs[r][c + 3] = v.w;
        }
        __syncthreads();
#pragma unroll
        for (int kk = 0; kk < 32; kk++) {
            float xv = Xs[ti][kk];
#pragma unroll
            for (int u = 0; u < 8; u++) acc[u] += xv * Ms[si * 8 + u][kk];
        }
        __syncthreads();
    }

#pragma unroll
    for (int u = 0; u < 8; u++) acc[u] = tanhf(acc[u] * um[si * 8 + u]);
    float mx = -1e30f;
#pragma unroll
    for (int u = 0; u < 8; u++) mx = fmaxf(mx, acc[u]);
    for (int o = 8; o >= 1; o >>= 1) mx = fmaxf(mx, __shfl_xor_sync(0xffffffffu, mx, o, 16));
    float a[8]; float s2 = 0.0f;
#pragma unroll
    for (int u = 0; u < 8; u++) {
        a[u] = expf(acc[u] - mx) * um[si * 8 + u];
        s2 += a[u];
    }
    for (int o = 8; o >= 1; o >>= 1) s2 += __shfl_xor_sync(0xffffffffu, s2, o, 16);
    float inv = 1.0f / s2;
#pragma unroll
    for (int u = 0; u < 8; u++) Aa[ti][si * 8 + u] = a[u] * inv;
    __syncthreads();

    for (int d0 = 0; d0 < DD2; d0 += 32) {
        {
            int s = tid >> 1;
            const float* mrow = M + ((size_t)(s * BBS + b)) * DD2 + d0;
#pragma unroll
            for (int i = 0; i < 4; i++) {
                int c = (tid & 1) * 16 + i * 4;
                float4 v = *(const float4*)(mrow + c);
                Ms[s][c] = v.x; Ms[s][c + 1] = v.y; Ms[s][c + 2] = v.z; Ms[s][c + 3] = v.w;
            }
        }
        __syncthreads();
        int dloc = (tid & 15) * 2;
        float r0 = 0.f, r1 = 0.f;
#pragma unroll 8
        for (int s = 0; s < 128; s++) {
            float al = Aa[ti][s];
            r0 += al * Ms[s][dloc];
            r1 += al * Ms[s][dloc + 1];
        }
        float* orow = att + ((size_t)((t0 + ti) * BBS + b)) * DD2 + d0 + dloc;
        orow[0] = r0; orow[1] = r1;
        __syncthreads();
    }
}

// ---------------- launch ----------------
extern "C" void kernel_launch(void* const* d_in, const int* in_sizes, int n_in,
                              void* d_out, int out_size) {
    const float* feat   = (const float*)d_in[0];
    const int*   ei     = (const int*)d_in[1];
    const int*   et     = (const int*)d_in[2];
    const float* umask  = (const float*)d_in[4];
    const float* Wrel   = (const float*)d_in[5];
    const float* Wroot  = (const float*)d_in[6];
    const float* rb     = (const float*)d_in[7];
    const float* gcWrel = (const float*)d_in[8];
    const float* gcWroot= (const float*)d_in[9];
    const float* gcb    = (const float*)d_in[10];
    const float* Wih0   = (const float*)d_in[11];
    const float* Whh0   = (const float*)d_in[12];
    const float* b0     = (const float*)d_in[13];
    const float* Wih1   = (const float*)d_in[14];
    const float* Whh1   = (const float*)d_in[15];
    const float* b1     = (const float*)d_in[16];
    const float* mattW  = (const float*)d_in[17];
    const float* mattb  = (const float*)d_in[18];
    const float* linW   = (const float*)d_in[19];
    const float* linb   = (const float*)d_in[20];
    float* out = (float*)d_out;

    float *hrel, *out1, *cnt, *agg, *out2, *x0, *g0, *h0, *g1, *Mb, *Xb, *attb, *barp;
    u64 *ws, *hsp;
    cudaGetSymbolAddress((void**)&hrel, g_hrel);
    cudaGetSymbolAddress((void**)&out1, g_out1);
    cudaGetSymbolAddress((void**)&cnt,  g_cnt);
    cudaGetSymbolAddress((void**)&agg,  g_agg);
    cudaGetSymbolAddress((void**)&out2, g_out2);
    cudaGetSymbolAddress((void**)&x0,   g_x0);
    cudaGetSymbolAddress((void**)&g0,   g_g0);
    cudaGetSymbolAddress((void**)&h0,   g_h0);
    cudaGetSymbolAddress((void**)&g1,   g_g1);
    cudaGetSymbolAddress((void**)&Mb,   g_M);
    cudaGetSymbolAddress((void**)&Xb,   g_X);
    cudaGetSymbolAddress((void**)&attb, g_att);
    cudaGetSymbolAddress((void**)&barp, g_bar);
    cudaGetSymbolAddress((void**)&ws,   g_ws);
    cudaGetSymbolAddress((void**)&hsp,  g_hs);

    cudaFuncSetAttribute(lstm_tc_kernel,
                         cudaFuncAttributeMaxDynamicSharedMemorySize, SMEM_TLSTM);

    const int WN = 2 * GG4 * DHH;          // Whh elements per layer
    const int HSF = 2 * 2 * BBS * DHH * 2; // g_hs float count

    // --- graph stage ---
    fill_zero_kernel<<<(NN * RRE + 255) / 256, 256>>>(cnt, NN * RRE);
    fill_zero_kernel<<<(NN * HIDN + 255) / 256, 256>>>(agg, NN * HIDN);
    count_kernel<<<EE / 256, 256>>>(ei, et, cnt);
    tgemm_kernel<false, false><<<dim3(4, 32, 1), 256>>>(feat, Wroot, rb, out1,
        NN, HIDN, FIN, 0, 0, 0, 0, 0);
    tgemm_kernel<false, false><<<dim3(4, 32, RRE), 256>>>(feat, Wrel, nullptr, hrel,
        NN, HIDN, FIN, 0, (size_t)FIN * HIDN, 0, (size_t)NN * HIDN, 0);
    rgcn_scatter_kernel<<<EE / 4, 256>>>(hrel, ei, et, cnt, out1);
    gconv_scatter_kernel<<<EE / 4, 256>>>(out1, ei, agg);
    tgemm_kernel<false, false><<<dim3(4, 32, 1), 256>>>(agg, gcWrel, gcb, out2,
        NN, HIDN, HIDN, 0, 0, 0, 0, 0);
    tgemm_kernel<false, false><<<dim3(4, 32, 1), 256>>>(out1, gcWroot, nullptr, out2,
        NN, HIDN, HIDN, 0, 0, 0, 0, 1);
    concat_kernel<<<NN, 256>>>(feat, out2, x0);

    // --- BiLSTM layer 0 ---
    tgemm_kernel<true, false><<<dim3(48, 32, 2), 256>>>(x0, Wih0, b0, g0,
        NN, GG4, DHH, 0, (size_t)GG4 * DHH, GG4, (size_t)NN * GG4, 0);
    wsplit_kernel<<<(WN + 255) / 256, 256>>>(Whh0, ws, WN);
    fill_zero_kernel<<<(HSF + 255) / 256, 256>>>((float*)hsp, HSF);
    fill_zero_kernel<<<1, 256>>>(barp, 2);
    lstm_tc_kernel<<<NBLK, 256, SMEM_TLSTM>>>(ws, g0, hsp, h0);

    // --- BiLSTM layer 1 ---
    tgemm_kernel<true, false><<<dim3(48, 32, 2), 256>>>(h0, Wih1, b1, g1,
        NN, GG4, DD2, 0, (size_t)GG4 * DD2, GG4, (size_t)NN * GG4, 0);
    wsplit_kernel<<<(WN + 255) / 256, 256>>>(Whh1, ws, WN);
    fill_zero_kernel<<<(HSF + 255) / 256, 256>>>((float*)hsp, HSF);
    fill_zero_kernel<<<1, 256>>>(barp, 2);
    lstm_tc_kernel<<<NBLK, 256, SMEM_TLSTM>>>(ws, g1, hsp, Mb);

    // --- attention + output ---
    tgemm_kernel<true, false><<<dim3(24, 32, 1), 256>>>(Mb, mattW, mattb, Xb,
        NN, DD2, DD2, 0, 0, 0, 0, 0);
    attention_kernel<<<dim3(8, 32), 256>>>(Mb, Xb, umask, attb);
    tgemm_kernel<true, true><<<dim3(12, 32, 1), 256>>>(attb, linW, linb, out,
        NN, DHH, DD2, 0, 0, 0, 0, 0);
}

// round 10
// speedup vs baseline: 2.4815x; 1.6108x over previous
#include <cuda_runtime.h>
#include <math.h>

#define NN    4096
#define FIN   512
#define HIDN  256
#define RRE   16
#define EE    65536
#define BBS   32
#define SSEQ  128
#define DHH   768
#define DD2   1536
#define GG4   3072

typedef unsigned long long u64;
typedef unsigned int u32;

// ---------------- tf32 helpers ----------------
__device__ __forceinline__ u32 cvtf(float x) {
    u32 r; asm("cvt.rna.tf32.f32 %0, %1;" : "=r"(r) : "f"(x)); return r;
}
__device__ __forceinline__ void split_tf32(float x, u32& hi, u32& lo) {
    hi = cvtf(x);
    lo = cvtf(x - __uint_as_float(hi));
}
__device__ __forceinline__ void mma8(float* d, const u32* a, const u32* b) {
    asm("mma.sync.aligned.m16n8k8.row.col.f32.tf32.tf32.f32 "
        "{%0,%1,%2,%3}, {%4,%5,%6,%7}, {%8,%9}, {%0,%1,%2,%3};"
        : "+f"(d[0]), "+f"(d[1]), "+f"(d[2]), "+f"(d[3])
        : "r"(a[0]), "r"(a[1]), "r"(a[2]), "r"(a[3]), "r"(b[0]), "r"(b[1]));
}

// ---------------- device scratch ----------------
__device__ float g_hrel[(size_t)RRE * NN * HIDN];
__device__ float g_out1[(size_t)NN * HIDN];
__device__ float g_cnt[(size_t)NN * RRE];
__device__ float g_agg[(size_t)NN * HIDN];
__device__ float g_out2[(size_t)NN * HIDN];
__device__ float g_x0[(size_t)NN * DHH];
__device__ float g_g0[(size_t)2 * NN * GG4];
__device__ float g_h0[(size_t)NN * DD2];
__device__ float g_g1[(size_t)2 * NN * GG4];
__device__ float g_M[(size_t)NN * DD2];
__device__ float g_X[(size_t)NN * DD2];
__device__ float g_att[(size_t)NN * DD2];
__device__ u32 g_whi[(size_t)2 * GG4 * DHH];    // Whh tf32 hi
__device__ u32 g_wlo[(size_t)2 * GG4 * DHH];    // Whh tf32 lo
__device__ float g_hf[(size_t)2 * 2 * BBS * DHH]; // h state [parity][dir][b][k], f32
__device__ unsigned g_bar[2];                   // cnt, gen

__global__ void fill_zero_kernel(float* p, int n) {
    int i = blockIdx.x * 256 + threadIdx.x;
    if (i < n) p[i] = 0.0f;
}

__device__ __forceinline__ float sigf(float x) { return 1.0f / (1.0f + expf(-x)); }

// ---------------- 3xTF32 tensor-core GEMM ----------------
template<bool TRANSB, bool RELU>
__global__ __launch_bounds__(256) void tgemm_kernel(
    const float* __restrict__ A, const float* __restrict__ B,
    const float* __restrict__ bias, float* __restrict__ C,
    int M, int N, int K,
    size_t sA, size_t sB, size_t sBias, size_t sC, int addC)
{
    A += (size_t)blockIdx.z * sA;
    B += (size_t)blockIdx.z * sB;
    C += (size_t)blockIdx.z * sC;
    const float* bi = bias ? bias + (size_t)blockIdx.z * sBias : (const float*)0;

    __shared__ u32 Ah[128][20];
    __shared__ u32 Al[128][20];
    __shared__ u32 Bh[16][76];
    __shared__ u32 Bl[16][76];
    const int m0 = blockIdx.y * 128, n0 = blockIdx.x * 64;
    const int tid = threadIdx.x;
    const int lane = tid & 31, wid = tid >> 5;
    const int wm = (wid & 3) * 32, wn = (wid >> 2) * 32;
    const int g = lane >> 2, tig = lane & 3;

    float acc[2][4][4];
#pragma unroll
    for (int mt = 0; mt < 2; mt++)
#pragma unroll
        for (int nt = 0; nt < 4; nt++)
#pragma unroll
            for (int q = 0; q < 4; q++) acc[mt][nt][q] = 0.0f;

    for (int k0 = 0; k0 < K; k0 += 16) {
        {
            int ar = tid >> 1, ak = (tid & 1) * 8;
            const float* ap = A + (size_t)(m0 + ar) * K + k0 + ak;
            float4 v0 = *(const float4*)ap, v1 = *(const float4*)(ap + 4);
            uint4 qh, ql;
            split_tf32(v0.x, qh.x, ql.x); split_tf32(v0.y, qh.y, ql.y);
            split_tf32(v0.z, qh.z, ql.z); split_tf32(v0.w, qh.w, ql.w);
            *(uint4*)&Ah[ar][ak] = qh; *(uint4*)&Al[ar][ak] = ql;
            split_tf32(v1.x, qh.x, ql.x); split_tf32(v1.y, qh.y, ql.y);
            split_tf32(v1.z, qh.z, ql.z); split_tf32(v1.w, qh.w, ql.w);
            *(uint4*)&Ah[ar][ak + 4] = qh; *(uint4*)&Al[ar][ak + 4] = ql;
        }
        if (TRANSB) {
            int br = tid >> 2, bk = (tid & 3) * 4;
            const float* bp = B + (size_t)(n0 + br) * K + k0 + bk;
            float4 v = *(const float4*)bp;
            u32 h, l;
            split_tf32(v.x, h, l); Bh[bk + 0][br] = h; Bl[bk + 0][br] = l;
            split_tf32(v.y, h, l); Bh[bk + 1][br] = h; Bl[bk + 1][br] = l;
            split_tf32(v.z, h, l); Bh[bk + 2][br] = h; Bl[bk + 2][br] = l;
            split_tf32(v.w, h, l); Bh[bk + 3][br] = h; Bl[bk + 3][br] = l;
        } else {
            int bk = tid >> 4, bn = (tid & 15) * 4;
            const float* bp = B + (size_t)(k0 + bk) * N + n0 + bn;
            float4 v = *(const float4*)bp;
            uint4 qh, ql;
            split_tf32(v.x, qh.x, ql.x); split_tf32(v.y, qh.y, ql.y);
            split_tf32(v.z, qh.z, ql.z); split_tf32(v.w, qh.w, ql.w);
            *(uint4*)&Bh[bk][bn] = qh; *(uint4*)&Bl[bk][bn] = ql;
        }
        __syncthreads();
#pragma unroll
        for (int ks = 0; ks < 2; ks++) {
            const int kb = ks * 8;
            u32 afh[2][4], afl[2][4], bfh[4][2], bfl[4][2];
#pragma unroll
            for (int mt = 0; mt < 2; mt++) {
                int r = wm + mt * 16 + g;
                afh[mt][0] = Ah[r][kb + tig];
                afh[mt][1] = Ah[r + 8][kb + tig];
                afh[mt][2] = Ah[r][kb + tig + 4];
                afh[mt][3] = Ah[r + 8][kb + tig + 4];
                afl[mt][0] = Al[r][kb + tig];
                afl[mt][1] = Al[r + 8][kb + tig];
                afl[mt][2] = Al[r][kb + tig + 4];
                afl[mt][3] = Al[r + 8][kb + tig + 4];
            }
#pragma unroll
            for (int nt = 0; nt < 4; nt++) {
                bfh[nt][0] = Bh[kb + tig][wn + nt * 8 + g];
                bfh[nt][1] = Bh[kb + tig + 4][wn + nt * 8 + g];
                bfl[nt][0] = Bl[kb + tig][wn + nt * 8 + g];
                bfl[nt][1] = Bl[kb + tig + 4][wn + nt * 8 + g];
            }
#pragma unroll
            for (int mt = 0; mt < 2; mt++)
#pragma unroll
                for (int nt = 0; nt < 4; nt++) {
                    mma8(acc[mt][nt], afl[mt], bfh[nt]);
                    mma8(acc[mt][nt], afh[mt], bfl[nt]);
                    mma8(acc[mt][nt], afh[mt], bfh[nt]);
                }
        }
        __syncthreads();
    }
#pragma unroll
    for (int mt = 0; mt < 2; mt++) {
#pragma unroll
        for (int nt = 0; nt < 4; nt++) {
            int c = n0 + wn + nt * 8 + 2 * tig;
#pragma unroll
            for (int h = 0; h < 2; h++) {
                int r = m0 + wm + mt * 16 + g + h * 8;
                float2 v = make_float2(acc[mt][nt][h * 2], acc[mt][nt][h * 2 + 1]);
                if (bi) { v.x += bi[c]; v.y += bi[c + 1]; }
                float2* cp = (float2*)&C[(size_t)r * N + c];
                if (addC) { float2 o = *cp; v.x += o.x; v.y += o.y; }
                if (RELU) { v.x = fmaxf(v.x, 0.f); v.y = fmaxf(v.y, 0.f); }
                *cp = v;
            }
        }
    }
}

// ---------------- graph kernels ----------------
__global__ void count_kernel(const int* __restrict__ ei, const int* __restrict__ et,
                             float* __restrict__ cnt) {
    int e = blockIdx.x * 256 + threadIdx.x;
    if (e < EE) atomicAdd(&cnt[ei[EE + e] * RRE + et[e]], 1.0f);
}

__global__ void rgcn_scatter_kernel(const float* __restrict__ hrel, const int* __restrict__ ei,
                                    const int* __restrict__ et, const float* __restrict__ cnt,
                                    float* __restrict__ out1) {
    int e = blockIdx.x * 4 + (threadIdx.x >> 6);
    int lane = threadIdx.x & 63;
    int src = ei[e], dst = ei[EE + e], r = et[e];
    float inv = 1.0f / fmaxf(cnt[dst * RRE + r], 1.0f);
    float4 v = ((const float4*)(hrel + ((size_t)r * NN + src) * HIDN))[lane];
    float* o = out1 + (size_t)dst * HIDN + lane * 4;
    atomicAdd(o + 0, v.x * inv);
    atomicAdd(o + 1, v.y * inv);
    atomicAdd(o + 2, v.z * inv);
    atomicAdd(o + 3, v.w * inv);
}

__global__ void gconv_scatter_kernel(const float* __restrict__ out1, const int* __restrict__ ei,
                                     float* __restrict__ agg) {
    int e = blockIdx.x * 4 + (threadIdx.x >> 6);
    int lane = threadIdx.x & 63;
    int src = ei[e], dst = ei[EE + e];
    float4 v = ((const float4*)(out1 + (size_t)src * HIDN))[lane];
    float* o = agg + (size_t)dst * HIDN + lane * 4;
    atomicAdd(o + 0, v.x);
    atomicAdd(o + 1, v.y);
    atomicAdd(o + 2, v.z);
    atomicAdd(o + 3, v.w);
}

__global__ void concat_kernel(const float* __restrict__ feat, const float* __restrict__ out2,
                              float* __restrict__ x0) {
    int n = blockIdx.x;
    int b = n >> 7, s = n & 127;
    float* dstrow = x0 + (size_t)(s * BBS + b) * DHH;
    for (int d = threadIdx.x; d < DHH; d += 256)
        dstrow[d] = (d < FIN) ? feat[(size_t)n * FIN + d] : out2[(size_t)n * HIDN + (d - FIN)];
}

// ---------------- persistent tensor-core BiLSTM (W-hi in smem) ----------------
#define NBLK 128
#define WST  772   // Whi smem row stride (772%32=4 -> conflict-free fragments)
#define PCOLS 52
#define SMEM_TLSTM ((48 * WST + 8 * 32 * PCOLS + 32 * PCOLS) * 4)

__device__ __forceinline__ void gbar(unsigned phase) {
    __syncthreads();
    if (threadIdx.x == 0) {
        __threadfence();
        unsigned a = atomicAdd(&g_bar[0], 1u);
        if (a == NBLK - 1u) {
            g_bar[0] = 0u;
            __threadfence();
            atomicExch(&g_bar[1], phase + 1u);
        } else {
            while (atomicAdd(&g_bar[1], 0u) <= phase) __nanosleep(32);
        }
        __threadfence();
    }
    __syncthreads();
}

// split Whh into separate hi/lo u32 arrays
__global__ void wsplit_kernel(const float* __restrict__ W, u32* __restrict__ whi,
                              u32* __restrict__ wlo, int n) {
    int i = blockIdx.x * 256 + threadIdx.x;
    if (i < n) {
        u32 h, l; split_tf32(W[i], h, l);
        whi[i] = h; wlo[i] = l;
    }
}

// grid = 128 (dir = bx&1, j0 = (bx>>1)*12), 256 threads (8 warps K-split).
// Block owns 12 hidden units x 4 gates = 48 gate cols; W-hi cached in smem.
__global__ __launch_bounds__(256) void lstm_tc_kernel(
    const u32* __restrict__ Whi, const u32* __restrict__ Wlo,
    const float* __restrict__ gpre,
    float* __restrict__ hf, float* __restrict__ hout)
{
    extern __shared__ u32 smu[];
    u32* whi = smu;                              // [48][WST]
    float* part = (float*)(smu + 48 * WST);      // [8][32][PCOLS]
    float* gsum = part + 8 * 32 * PCOLS;         // [32][PCOLS]

    const int bx = blockIdx.x;
    const int dir = bx & 1;
    const int j0 = (bx >> 1) * 12;
    const int tid = threadIdx.x;
    const int w = tid >> 5, lane = tid & 31;
    const int g = lane >> 2, tig = lane & 3;

    const u32* WhiG = Whi + (size_t)dir * GG4 * DHH;
    const u32* WloG = Wlo + (size_t)dir * GG4 * DHH;

    // stage W-hi slice into smem once (reused all 128 steps)
    for (int idx = tid; idx < 48 * DHH; idx += 256) {
        int c = idx / DHH, k = idx % DHH;
        int row = (c / 12) * DHH + j0 + (c % 12);
        whi[c * WST + k] = WhiG[(size_t)row * DHH + k];
    }
    // per-lane W-lo row pointers + smem col per n-group
    const u32* wlop[6];
    int ccol[6];
#pragma unroll
    for (int nt = 0; nt < 6; nt++) {
        int c = nt * 8 + g;
        int row = (c / 12) * DHH + j0 + (c % 12);
        wlop[nt] = WloG + (size_t)row * DHH;
        ccol[nt] = c;
    }
    __syncthreads();

    float cst[2] = {0.0f, 0.0f};

    for (int t = 0; t < SSEQ; t++) {
        const float* hin = hf + ((size_t)(t & 1) * 2 + dir) * (BBS * DHH);
        float* hOut      = hf + ((size_t)((t + 1) & 1) * 2 + dir) * (BBS * DHH);

        float acc[2][6][4];
#pragma unroll
        for (int mt = 0; mt < 2; mt++)
#pragma unroll
            for (int nt = 0; nt < 6; nt++)
#pragma unroll
                for (int q = 0; q < 4; q++) acc[mt][nt][q] = 0.0f;

        const int kw = w * 96;
#pragma unroll
        for (int s = 0; s < 12; s++) {
            const int k0 = kw + s * 8;
            u32 ah[2][4], al[2][4];
#pragma unroll
            for (int mt = 0; mt < 2; mt++) {
                int r0 = mt * 16 + g;
                float f0 = hin[r0 * DHH + k0 + tig];
                float f1 = hin[(r0 + 8) * DHH + k0 + tig];
                float f2 = hin[r0 * DHH + k0 + tig + 4];
                float f3 = hin[(r0 + 8) * DHH + k0 + tig + 4];
                split_tf32(f0, ah[mt][0], al[mt][0]);
                split_tf32(f1, ah[mt][1], al[mt][1]);
                split_tf32(f2, ah[mt][2], al[mt][2]);
                split_tf32(f3, ah[mt][3], al[mt][3]);
            }
#pragma unroll
            for (int nt = 0; nt < 6; nt++) {
                u32 bh[2], bl[2];
                bh[0] = whi[ccol[nt] * WST + k0 + tig];
                bh[1] = whi[ccol[nt] * WST + k0 + tig + 4];
                bl[0] = wlop[nt][k0 + tig];
                bl[1] = wlop[nt][k0 + tig + 4];
#pragma unroll
                for (int mt = 0; mt < 2; mt++) {
                    mma8(acc[mt][nt], al[mt], bh);
                    mma8(acc[mt][nt], ah[mt], bl);
                    mma8(acc[mt][nt], ah[mt], bh);
                }
            }
        }
        // store K-partials
#pragma unroll
        for (int mt = 0; mt < 2; mt++)
#pragma unroll
            for (int nt = 0; nt < 6; nt++) {
                int b0 = mt * 16 + g, c = nt * 8 + 2 * tig;
                float* p0 = &part[(w * 32 + b0) * PCOLS + c];
                p0[0] = acc[mt][nt][0]; p0[1] = acc[mt][nt][1];
                float* p1 = &part[(w * 32 + b0 + 8) * PCOLS + c];
                p1[0] = acc[mt][nt][2]; p1[1] = acc[mt][nt][3];
            }
        __syncthreads();
        // reduce over 8 warps
        for (int q = tid; q < 32 * 48; q += 256) {
            int b = q / 48, c = q % 48;
            float sum = 0.0f;
#pragma unroll
            for (int ww = 0; ww < 8; ww++) sum += part[(ww * 32 + b) * PCOLS + c];
            gsum[b * PCOLS + c] = sum;
        }
        __syncthreads();
        // gate nonlinearity + state update (384 (b,jl) pairs)
        const int tdir = dir ? (SSEQ - 1 - t) : t;
#pragma unroll
        for (int u = 0; u < 2; u++) {
            int pr = tid + u * 256;
            if (pr < 384) {
                int b = pr / 12, jl = pr % 12;
                int j = j0 + jl;
                int row = tdir * BBS + b;
                const float* gp = gpre + ((size_t)dir * NN + row) * GG4;
                float gi = gsum[b * PCOLS + jl]      + gp[j];
                float gf = gsum[b * PCOLS + 12 + jl] + gp[DHH + j];
                float gg = gsum[b * PCOLS + 24 + jl] + gp[2 * DHH + j];
                float go = gsum[b * PCOLS + 36 + jl] + gp[3 * DHH + j];
                float c2 = sigf(gf) * cst[u] + sigf(gi) * tanhf(gg);
                cst[u] = c2;
                float h = sigf(go) * tanhf(c2);
                hout[(size_t)row * DD2 + dir * DHH + j] = h;
                hOut[b * DHH + j] = h;
            }
        }
        gbar((unsigned)t);
    }
}

// ---------------- attention ----------------
__global__ __launch_bounds__(256) void attention_kernel(
    const float* __restrict__ M, const float* __restrict__ X,
    const float* __restrict__ umask, float* __restrict__ att)
{
    const int b = blockIdx.y;
    const int t0 = blockIdx.x * 16;
    const int tid = threadIdx.x;
    const int ti = tid >> 4, si = tid & 15;

    __shared__ float Ms[128][33];
    __shared__ float Xs[16][33];
    __shared__ float Aa[16][129];
    __shared__ float um[128];
    if (tid < 128) um[tid] = umask[b * SSEQ + tid];
    __syncthreads();

    float acc[8];
#pragma unroll
    for (int u = 0; u < 8; u++) acc[u] = 0.0f;

    for (int k0 = 0; k0 < DD2; k0 += 32) {
        {
            int s = tid >> 1;
            float u = um[s];
            const float* mrow = M + ((size_t)(s * BBS + b)) * DD2 + k0;
#pragma unroll
            for (int i = 0; i < 4; i++) {
                int c = (tid & 1) * 16 + i * 4;
                float4 v = *(const float4*)(mrow + c);
                Ms[s][c] = v.x * u; Ms[s][c + 1] = v.y * u;
                Ms[s][c + 2] = v.z * u; Ms[s][c + 3] = v.w * u;
            }
        }
        if (tid < 128) {
            int r = tid >> 3, c = (tid & 7) * 4;
            float4 v = *(const float4*)(X + ((size_t)((t0 + r) * BBS + b)) * DD2 + k0 + c);
            Xs[r][c] = v.x; Xs[r][c + 1] = v.y; Xs[r][c + 2] = v.z; Xs[r][c + 3] = v.w;
        }
        __syncthreads();
#pragma unroll
        for (int kk = 0; kk < 32; kk++) {
            float xv = Xs[ti][kk];
#pragma unroll
            for (int u = 0; u < 8; u++) acc[u] += xv * Ms[si * 8 + u][kk];
        }
        __syncthreads();
    }

#pragma unroll
    for (int u = 0; u < 8; u++) acc[u] = tanhf(acc[u] * um[si * 8 + u]);
    float mx = -1e30f;
#pragma unroll
    for (int u = 0; u < 8; u++) mx = fmaxf(mx, acc[u]);
    for (int o = 8; o >= 1; o >>= 1) mx = fmaxf(mx, __shfl_xor_sync(0xffffffffu, mx, o, 16));
    float a[8]; float s2 = 0.0f;
#pragma unroll
    for (int u = 0; u < 8; u++) {
        a[u] = expf(acc[u] - mx) * um[si * 8 + u];
        s2 += a[u];
    }
    for (int o = 8; o >= 1; o >>= 1) s2 += __shfl_xor_sync(0xffffffffu, s2, o, 16);
    float inv = 1.0f / s2;
#pragma unroll
    for (int u = 0; u < 8; u++) Aa[ti][si * 8 + u] = a[u] * inv;
    __syncthreads();

    for (int d0 = 0; d0 < DD2; d0 += 32) {
        {
            int s = tid >> 1;
            const float* mrow = M + ((size_t)(s * BBS + b)) * DD2 + d0;
#pragma unroll
            for (int i = 0; i < 4; i++) {
                int c = (tid & 1) * 16 + i * 4;
                float4 v = *(const float4*)(mrow + c);
                Ms[s][c] = v.x; Ms[s][c + 1] = v.y; Ms[s][c + 2] = v.z; Ms[s][c + 3] = v.w;
            }
        }
        __syncthreads();
        int dloc = (tid & 15) * 2;
        float r0 = 0.f, r1 = 0.f;
#pragma unroll 8
        for (int s = 0; s < 128; s++) {
            float al = Aa[ti][s];
            r0 += al * Ms[s][dloc];
            r1 += al * Ms[s][dloc + 1];
        }
        float* orow = att + ((size_t)((t0 + ti) * BBS + b)) * DD2 + d0 + dloc;
        orow[0] = r0; orow[1] = r1;
        __syncthreads();
    }
}

// ---------------- launch ----------------
extern "C" void kernel_launch(void* const* d_in, const int* in_sizes, int n_in,
                              void* d_out, int out_size) {
    const float* feat   = (const float*)d_in[0];
    const int*   ei     = (const int*)d_in[1];
    const int*   et     = (const int*)d_in[2];
    const float* umask  = (const float*)d_in[4];
    const float* Wrel   = (const float*)d_in[5];
    const float* Wroot  = (const float*)d_in[6];
    const float* rb     = (const float*)d_in[7];
    const float* gcWrel = (const float*)d_in[8];
    const float* gcWroot= (const float*)d_in[9];
    const float* gcb    = (const float*)d_in[10];
    const float* Wih0   = (const float*)d_in[11];
    const float* Whh0   = (const float*)d_in[12];
    const float* b0     = (const float*)d_in[13];
    const float* Wih1   = (const float*)d_in[14];
    const float* Whh1   = (const float*)d_in[15];
    const float* b1     = (const float*)d_in[16];
    const float* mattW  = (const float*)d_in[17];
    const float* mattb  = (const float*)d_in[18];
    const float* linW   = (const float*)d_in[19];
    const float* linb   = (const float*)d_in[20];
    float* out = (float*)d_out;

    float *hrel, *out1, *cnt, *agg, *out2, *x0, *g0, *h0, *g1, *Mb, *Xb, *attb, *barp, *hfp;
    u32 *whi, *wlo;
    cudaGetSymbolAddress((void**)&hrel, g_hrel);
    cudaGetSymbolAddress((void**)&out1, g_out1);
    cudaGetSymbolAddress((void**)&cnt,  g_cnt);
    cudaGetSymbolAddress((void**)&agg,  g_agg);
    cudaGetSymbolAddress((void**)&out2, g_out2);
    cudaGetSymbolAddress((void**)&x0,   g_x0);
    cudaGetSymbolAddress((void**)&g0,   g_g0);
    cudaGetSymbolAddress((void**)&h0,   g_h0);
    cudaGetSymbolAddress((void**)&g1,   g_g1);
    cudaGetSymbolAddress((void**)&Mb,   g_M);
    cudaGetSymbolAddress((void**)&Xb,   g_X);
    cudaGetSymbolAddress((void**)&attb, g_att);
    cudaGetSymbolAddress((void**)&barp, (const void*)g_bar);
    cudaGetSymbolAddress((void**)&whi,  g_whi);
    cudaGetSymbolAddress((void**)&wlo,  g_wlo);
    cudaGetSymbolAddress((void**)&hfp,  g_hf);

    cudaFuncSetAttribute(lstm_tc_kernel,
                         cudaFuncAttributeMaxDynamicSharedMemorySize, SMEM_TLSTM);

    const int WN = 2 * GG4 * DHH;        // Whh elements per layer
    const int HSF = 2 * 2 * BBS * DHH;   // g_hf float count

    // --- graph stage ---
    fill_zero_kernel<<<(NN * RRE + 255) / 256, 256>>>(cnt, NN * RRE);
    fill_zero_kernel<<<(NN * HIDN + 255) / 256, 256>>>(agg, NN * HIDN);
    count_kernel<<<EE / 256, 256>>>(ei, et, cnt);
    tgemm_kernel<false, false><<<dim3(4, 32, 1), 256>>>(feat, Wroot, rb, out1,
        NN, HIDN, FIN, 0, 0, 0, 0, 0);
    tgemm_kernel<false, false><<<dim3(4, 32, RRE), 256>>>(feat, Wrel, nullptr, hrel,
        NN, HIDN, FIN, 0, (size_t)FIN * HIDN, 0, (size_t)NN * HIDN, 0);
    rgcn_scatter_kernel<<<EE / 4, 256>>>(hrel, ei, et, cnt, out1);
    gconv_scatter_kernel<<<EE / 4, 256>>>(out1, ei, agg);
    tgemm_kernel<false, false><<<dim3(4, 32, 1), 256>>>(agg, gcWrel, gcb, out2,
        NN, HIDN, HIDN, 0, 0, 0, 0, 0);
    tgemm_kernel<false, false><<<dim3(4, 32, 1), 256>>>(out1, gcWroot, nullptr, out2,
        NN, HIDN, HIDN, 0, 0, 0, 0, 1);
    concat_kernel<<<NN, 256>>>(feat, out2, x0);

    // --- BiLSTM layer 0 ---
    tgemm_kernel<true, false><<<dim3(48, 32, 2), 256>>>(x0, Wih0, b0, g0,
        NN, GG4, DHH, 0, (size_t)GG4 * DHH, GG4, (size_t)NN * GG4, 0);
    wsplit_kernel<<<(WN + 255) / 256, 256>>>(Whh0, whi, wlo, WN);
    fill_zero_kernel<<<(HSF + 255) / 256, 256>>>(hfp, HSF);
    fill_zero_kernel<<<1, 256>>>(barp, 2);
    lstm_tc_kernel<<<NBLK, 256, SMEM_TLSTM>>>(whi, wlo, g0, hfp, h0);

    // --- BiLSTM layer 1 ---
    tgemm_kernel<true, false><<<dim3(48, 32, 2), 256>>>(h0, Wih1, b1, g1,
        NN, GG4, DD2, 0, (size_t)GG4 * DD2, GG4, (size_t)NN * GG4, 0);
    wsplit_kernel<<<(WN + 255) / 256, 256>>>(Whh1, whi, wlo, WN);
    fill_zero_kernel<<<(HSF + 255) / 256, 256>>>(hfp, HSF);
    fill_zero_kernel<<<1, 256>>>(barp, 2);
    lstm_tc_kernel<<<NBLK, 256, SMEM_TLSTM>>>(whi, wlo, g1, hfp, Mb);

    // --- attention + output ---
    tgemm_kernel<true, false><<<dim3(24, 32, 1), 256>>>(Mb, mattW, mattb, Xb,
        NN, DD2, DD2, 0, 0, 0, 0, 0);
    attention_kernel<<<dim3(8, 32), 256>>>(Mb, Xb, umask, attb);
    tgemm_kernel<true, true><<<dim3(12, 32, 1), 256>>>(attb, linW, linb, out,
        NN, DHH, DD2, 0, 0, 0, 0, 0);
}

// round 11
// speedup vs baseline: 2.7923x; 1.1252x over previous
#include <cuda_runtime.h>
#include <math.h>

#define NN    4096
#define FIN   512
#define HIDN  256
#define RRE   16
#define EE    65536
#define BBS   32
#define SSEQ  128
#define DHH   768
#define DD2   1536
#define GG4   3072

typedef unsigned long long u64;
typedef unsigned int u32;

// ---------------- tf32 helpers ----------------
__device__ __forceinline__ u32 cvtf(float x) {
    u32 r; asm("cvt.rna.tf32.f32 %0, %1;" : "=r"(r) : "f"(x)); return r;
}
__device__ __forceinline__ void split_tf32(float x, u32& hi, u32& lo) {
    hi = cvtf(x);
    lo = cvtf(x - __uint_as_float(hi));
}
__device__ __forceinline__ void mma8(float* d, const u32* a, const u32* b) {
    asm("mma.sync.aligned.m16n8k8.row.col.f32.tf32.tf32.f32 "
        "{%0,%1,%2,%3}, {%4,%5,%6,%7}, {%8,%9}, {%0,%1,%2,%3};"
        : "+f"(d[0]), "+f"(d[1]), "+f"(d[2]), "+f"(d[3])
        : "r"(a[0]), "r"(a[1]), "r"(a[2]), "r"(a[3]), "r"(b[0]), "r"(b[1]));
}
__device__ __forceinline__ void cpa16(u32 dst, const void* src) {
    asm volatile("cp.async.ca.shared.global [%0], [%1], 16;" :: "r"(dst), "l"(src) : "memory");
}

// ---------------- device scratch ----------------
__device__ float g_hrel[(size_t)RRE * NN * HIDN];
__device__ float g_out1[(size_t)NN * HIDN];
__device__ float g_cnt[(size_t)NN * RRE];
__device__ float g_agg[(size_t)NN * HIDN];
__device__ float g_out2[(size_t)NN * HIDN];
__device__ float g_x0[(size_t)NN * DHH];
__device__ float g_g0[(size_t)2 * NN * GG4];
__device__ float g_h0[(size_t)NN * DD2];
__device__ float g_g1[(size_t)2 * NN * GG4];
__device__ float g_M[(size_t)NN * DD2];
__device__ float g_X[(size_t)NN * DD2];
__device__ float g_att[(size_t)NN * DD2];
__device__ u32 g_whi[(size_t)2 * GG4 * DHH];    // Whh tf32 hi
__device__ u32 g_wlo[(size_t)2 * GG4 * DHH];    // Whh tf32 lo
__device__ float g_hf[(size_t)2 * 2 * BBS * DHH]; // h state [parity][dir][b][k], f32
__device__ unsigned g_bar[2];                   // cnt, gen

__global__ void fill_zero_kernel(float* p, int n) {
    int i = blockIdx.x * 256 + threadIdx.x;
    if (i < n) p[i] = 0.0f;
}

__device__ __forceinline__ float sigf(float x) { return 1.0f / (1.0f + expf(-x)); }

// ---------------- 3xTF32 tensor-core GEMM, cp.async double-buffered ----------
// C[M,N] = act(A @ (TRANSB ? B^T : B) + bias + (addC ? C : 0)), z-batched.
// M mult of 128, N mult of 64, K mult of 16.
template<bool TRANSB, bool RELU>
__global__ __launch_bounds__(256, 2) void tgemm_kernel(
    const float* __restrict__ A, const float* __restrict__ B,
    const float* __restrict__ bias, float* __restrict__ C,
    int M, int N, int K,
    size_t sA, size_t sB, size_t sBias, size_t sC, int addC)
{
    A += (size_t)blockIdx.z * sA;
    B += (size_t)blockIdx.z * sB;
    C += (size_t)blockIdx.z * sC;
    const float* bi = bias ? bias + (size_t)blockIdx.z * sBias : (const float*)0;

    __shared__ __align__(16) float As[2][128 * 20];  // raw f32, 16 k-cols used
    __shared__ __align__(16) float Bs[2][1280];      // TRANSB: [64][20], else [16][68]

    const int m0 = blockIdx.y * 128, n0 = blockIdx.x * 64;
    const int tid = threadIdx.x;
    const int lane = tid & 31, wid = tid >> 5;
    const int wm = (wid & 3) * 32, wn = (wid >> 2) * 32;
    const int g = lane >> 2, tig = lane & 3;
    const int KT = K >> 4;

    const u32 sA0 = (u32)__cvta_generic_to_shared(&As[0][0]);
    const u32 sB0 = (u32)__cvta_generic_to_shared(&Bs[0][0]);

    float acc[2][4][4];
#pragma unroll
    for (int mt = 0; mt < 2; mt++)
#pragma unroll
        for (int nt = 0; nt < 4; nt++)
#pragma unroll
            for (int q = 0; q < 4; q++) acc[mt][nt][q] = 0.0f;

    auto issue = [&](int kt, int buf) {
        const int k0 = kt * 16;
        u32 da = sA0 + buf * (128 * 20 * 4);
        {   // A: 512 float4, 2 per thread
            int q0 = tid, q1 = tid + 256;
            int ar0 = q0 >> 2, ac0 = (q0 & 3) * 4;
            int ar1 = q1 >> 2, ac1 = (q1 & 3) * 4;
            cpa16(da + (ar0 * 20 + ac0) * 4, A + (size_t)(m0 + ar0) * K + k0 + ac0);
            cpa16(da + (ar1 * 20 + ac1) * 4, A + (size_t)(m0 + ar1) * K + k0 + ac1);
        }
        u32 db = sB0 + buf * (1280 * 4);
        if (TRANSB) {
            int br = tid >> 2, bc = (tid & 3) * 4;
            cpa16(db + (br * 20 + bc) * 4, B + (size_t)(n0 + br) * K + k0 + bc);
        } else {
            int bk = tid >> 4, bn = (tid & 15) * 4;
            cpa16(db + (bk * 68 + bn) * 4, B + (size_t)(k0 + bk) * N + n0 + bn);
        }
        asm volatile("cp.async.commit_group;" ::: "memory");
    };

    issue(0, 0);
    for (int kt = 0; kt < KT; kt++) {
        const int buf = kt & 1;
        if (kt + 1 < KT) {
            issue(kt + 1, buf ^ 1);
            asm volatile("cp.async.wait_group 1;" ::: "memory");
        } else {
            asm volatile("cp.async.wait_group 0;" ::: "memory");
        }
        __syncthreads();

        const float* Ab = &As[buf][0];
        const float* Bb = &Bs[buf][0];
#pragma unroll
        for (int ks = 0; ks < 2; ks++) {
            const int kb = ks * 8;
            u32 afh[2][4], afl[2][4], bfh[4][2], bfl[4][2];
#pragma unroll
            for (int mt = 0; mt < 2; mt++) {
                int r = wm + mt * 16 + g;
                float x0 = Ab[r * 20 + kb + tig];
                float x1 = Ab[(r + 8) * 20 + kb + tig];
                float x2 = Ab[r * 20 + kb + tig + 4];
                float x3 = Ab[(r + 8) * 20 + kb + tig + 4];
                split_tf32(x0, afh[mt][0], afl[mt][0]);
                split_tf32(x1, afh[mt][1], afl[mt][1]);
                split_tf32(x2, afh[mt][2], afl[mt][2]);
                split_tf32(x3, afh[mt][3], afl[mt][3]);
            }
#pragma unroll
            for (int nt = 0; nt < 4; nt++) {
                int c = wn + nt * 8 + g;
                float y0 = TRANSB ? Bb[c * 20 + kb + tig]     : Bb[(kb + tig) * 68 + c];
                float y1 = TRANSB ? Bb[c * 20 + kb + tig + 4] : Bb[(kb + tig + 4) * 68 + c];
                split_tf32(y0, bfh[nt][0], bfl[nt][0]);
                split_tf32(y1, bfh[nt][1], bfl[nt][1]);
            }
#pragma unroll
            for (int mt = 0; mt < 2; mt++)
#pragma unroll
                for (int nt = 0; nt < 4; nt++) {
                    mma8(acc[mt][nt], afl[mt], bfh[nt]);
                    mma8(acc[mt][nt], afh[mt], bfl[nt]);
                    mma8(acc[mt][nt], afh[mt], bfh[nt]);
                }
        }
        __syncthreads();
    }
#pragma unroll
    for (int mt = 0; mt < 2; mt++) {
#pragma unroll
        for (int nt = 0; nt < 4; nt++) {
            int c = n0 + wn + nt * 8 + 2 * tig;
#pragma unroll
            for (int h = 0; h < 2; h++) {
                int r = m0 + wm + mt * 16 + g + h * 8;
                float2 v = make_float2(acc[mt][nt][h * 2], acc[mt][nt][h * 2 + 1]);
                if (bi) { v.x += bi[c]; v.y += bi[c + 1]; }
                float2* cp = (float2*)&C[(size_t)r * N + c];
                if (addC) { float2 o = *cp; v.x += o.x; v.y += o.y; }
                if (RELU) { v.x = fmaxf(v.x, 0.f); v.y = fmaxf(v.y, 0.f); }
                *cp = v;
            }
        }
    }
}

// ---------------- graph kernels ----------------
__global__ void count_kernel(const int* __restrict__ ei, const int* __restrict__ et,
                             float* __restrict__ cnt) {
    int e = blockIdx.x * 256 + threadIdx.x;
    if (e < EE) atomicAdd(&cnt[ei[EE + e] * RRE + et[e]], 1.0f);
}

__global__ void rgcn_scatter_kernel(const float* __restrict__ hrel, const int* __restrict__ ei,
                                    const int* __restrict__ et, const float* __restrict__ cnt,
                                    float* __restrict__ out1) {
    int e = blockIdx.x * 4 + (threadIdx.x >> 6);
    int lane = threadIdx.x & 63;
    int src = ei[e], dst = ei[EE + e], r = et[e];
    float inv = 1.0f / fmaxf(cnt[dst * RRE + r], 1.0f);
    float4 v = ((const float4*)(hrel + ((size_t)r * NN + src) * HIDN))[lane];
    float* o = out1 + (size_t)dst * HIDN + lane * 4;
    atomicAdd(o + 0, v.x * inv);
    atomicAdd(o + 1, v.y * inv);
    atomicAdd(o + 2, v.z * inv);
    atomicAdd(o + 3, v.w * inv);
}

__global__ void gconv_scatter_kernel(const float* __restrict__ out1, const int* __restrict__ ei,
                                     float* __restrict__ agg) {
    int e = blockIdx.x * 4 + (threadIdx.x >> 6);
    int lane = threadIdx.x & 63;
    int src = ei[e], dst = ei[EE + e];
    float4 v = ((const float4*)(out1 + (size_t)src * HIDN))[lane];
    float* o = agg + (size_t)dst * HIDN + lane * 4;
    atomicAdd(o + 0, v.x);
    atomicAdd(o + 1, v.y);
    atomicAdd(o + 2, v.z);
    atomicAdd(o + 3, v.w);
}

__global__ void concat_kernel(const float* __restrict__ feat, const float* __restrict__ out2,
                              float* __restrict__ x0) {
    int n = blockIdx.x;
    int b = n >> 7, s = n & 127;
    float* dstrow = x0 + (size_t)(s * BBS + b) * DHH;
    for (int d = threadIdx.x; d < DHH; d += 256)
        dstrow[d] = (d < FIN) ? feat[(size_t)n * FIN + d] : out2[(size_t)n * HIDN + (d - FIN)];
}

// ---------------- persistent tensor-core BiLSTM (W-hi in smem) ----------------
#define NBLK 128
#define WST  772
#define PCOLS 52
#define SMEM_TLSTM ((48 * WST + 8 * 32 * PCOLS + 32 * PCOLS) * 4)

__device__ __forceinline__ void gbar(unsigned phase) {
    __syncthreads();
    if (threadIdx.x == 0) {
        __threadfence();
        unsigned a = atomicAdd(&g_bar[0], 1u);
        if (a == NBLK - 1u) {
            g_bar[0] = 0u;
            __threadfence();
            atomicExch(&g_bar[1], phase + 1u);
        } else {
            while (atomicAdd(&g_bar[1], 0u) <= phase) __nanosleep(32);
        }
        __threadfence();
    }
    __syncthreads();
}

__global__ void wsplit_kernel(const float* __restrict__ W, u32* __restrict__ whi,
                              u32* __restrict__ wlo, int n) {
    int i = blockIdx.x * 256 + threadIdx.x;
    if (i < n) {
        u32 h, l; split_tf32(W[i], h, l);
        whi[i] = h; wlo[i] = l;
    }
}

__global__ __launch_bounds__(256) void lstm_tc_kernel(
    const u32* __restrict__ Whi, const u32* __restrict__ Wlo,
    const float* __restrict__ gpre,
    float* __restrict__ hf, float* __restrict__ hout)
{
    extern __shared__ u32 smu[];
    u32* whi = smu;                              // [48][WST]
    float* part = (float*)(smu + 48 * WST);      // [8][32][PCOLS]
    float* gsum = part + 8 * 32 * PCOLS;         // [32][PCOLS]

    const int bx = blockIdx.x;
    const int dir = bx & 1;
    const int j0 = (bx >> 1) * 12;
    const int tid = threadIdx.x;
    const int w = tid >> 5, lane = tid & 31;
    const int g = lane >> 2, tig = lane & 3;

    const u32* WhiG = Whi + (size_t)dir * GG4 * DHH;
    const u32* WloG = Wlo + (size_t)dir * GG4 * DHH;

    for (int idx = tid; idx < 48 * DHH; idx += 256) {
        int c = idx / DHH, k = idx % DHH;
        int row = (c / 12) * DHH + j0 + (c % 12);
        whi[c * WST + k] = WhiG[(size_t)row * DHH + k];
    }
    const u32* wlop[6];
    int ccol[6];
#pragma unroll
    for (int nt = 0; nt < 6; nt++) {
        int c = nt * 8 + g;
        int row = (c / 12) * DHH + j0 + (c % 12);
        wlop[nt] = WloG + (size_t)row * DHH;
        ccol[nt] = c;
    }
    __syncthreads();

    float cst[2] = {0.0f, 0.0f};

    for (int t = 0; t < SSEQ; t++) {
        const float* hin = hf + ((size_t)(t & 1) * 2 + dir) * (BBS * DHH);
        float* hOut      = hf + ((size_t)((t + 1) & 1) * 2 + dir) * (BBS * DHH);

        float acc[2][6][4];
#pragma unroll
        for (int mt = 0; mt < 2; mt++)
#pragma unroll
            for (int nt = 0; nt < 6; nt++)
#pragma unroll
                for (int q = 0; q < 4; q++) acc[mt][nt][q] = 0.0f;

        const int kw = w * 96;
#pragma unroll
        for (int s = 0; s < 12; s++) {
            const int k0 = kw + s * 8;
            u32 ah[2][4], al[2][4];
#pragma unroll
            for (int mt = 0; mt < 2; mt++) {
                int r0 = mt * 16 + g;
                float f0 = hin[r0 * DHH + k0 + tig];
                float f1 = hin[(r0 + 8) * DHH + k0 + tig];
                float f2 = hin[r0 * DHH + k0 + tig + 4];
                float f3 = hin[(r0 + 8) * DHH + k0 + tig + 4];
                split_tf32(f0, ah[mt][0], al[mt][0]);
                split_tf32(f1, ah[mt][1], al[mt][1]);
                split_tf32(f2, ah[mt][2], al[mt][2]);
                split_tf32(f3, ah[mt][3], al[mt][3]);
            }
#pragma unroll
            for (int nt = 0; nt < 6; nt++) {
                u32 bh[2], bl[2];
                bh[0] = whi[ccol[nt] * WST + k0 + tig];
                bh[1] = whi[ccol[nt] * WST + k0 + tig + 4];
                bl[0] = wlop[nt][k0 + tig];
                bl[1] = wlop[nt][k0 + tig + 4];
#pragma unroll
                for (int mt = 0; mt < 2; mt++) {
                    mma8(acc[mt][nt], al[mt], bh);
                    mma8(acc[mt][nt], ah[mt], bl);
                    mma8(acc[mt][nt], ah[mt], bh);
                }
            }
        }
#pragma unroll
        for (int mt = 0; mt < 2; mt++)
#pragma unroll
            for (int nt = 0; nt < 6; nt++) {
                int b0 = mt * 16 + g, c = nt * 8 + 2 * tig;
                float* p0 = &part[(w * 32 + b0) * PCOLS + c];
                p0[0] = acc[mt][nt][0]; p0[1] = acc[mt][nt][1];
                float* p1 = &part[(w * 32 + b0 + 8) * PCOLS + c];
                p1[0] = acc[mt][nt][2]; p1[1] = acc[mt][nt][3];
            }
        __syncthreads();
        for (int q = tid; q < 32 * 48; q += 256) {
            int b = q / 48, c = q % 48;
            float sum = 0.0f;
#pragma unroll
            for (int ww = 0; ww < 8; ww++) sum += part[(ww * 32 + b) * PCOLS + c];
            gsum[b * PCOLS + c] = sum;
        }
        __syncthreads();
        const int tdir = dir ? (SSEQ - 1 - t) : t;
#pragma unroll
        for (int u = 0; u < 2; u++) {
            int pr = tid + u * 256;
            if (pr < 384) {
                int b = pr / 12, jl = pr % 12;
                int j = j0 + jl;
                int row = tdir * BBS + b;
                const float* gp = gpre + ((size_t)dir * NN + row) * GG4;
                float gi = gsum[b * PCOLS + jl]      + gp[j];
                float gf = gsum[b * PCOLS + 12 + jl] + gp[DHH + j];
                float gg = gsum[b * PCOLS + 24 + jl] + gp[2 * DHH + j];
                float go = gsum[b * PCOLS + 36 + jl] + gp[3 * DHH + j];
                float c2 = sigf(gf) * cst[u] + sigf(gi) * tanhf(gg);
                cst[u] = c2;
                float h = sigf(go) * tanhf(c2);
                hout[(size_t)row * DD2 + dir * DHH + j] = h;
                hOut[b * DHH + j] = h;
            }
        }
        gbar((unsigned)t);
    }
}

// ---------------- attention ----------------
__global__ __launch_bounds__(256) void attention_kernel(
    const float* __restrict__ M, const float* __restrict__ X,
    const float* __restrict__ umask, float* __restrict__ att)
{
    const int b = blockIdx.y;
    const int t0 = blockIdx.x * 16;
    const int tid = threadIdx.x;
    const int ti = tid >> 4, si = tid & 15;

    __shared__ float Ms[128][33];
    __shared__ float Xs[16][33];
    __shared__ float Aa[16][129];
    __shared__ float um[128];
    if (tid < 128) um[tid] = umask[b * SSEQ + tid];
    __syncthreads();

    float acc[8];
#pragma unroll
    for (int u = 0; u < 8; u++) acc[u] = 0.0f;

    for (int k0 = 0; k0 < DD2; k0 += 32) {
        {
            int s = tid >> 1;
            float u = um[s];
            const float* mrow = M + ((size_t)(s * BBS + b)) * DD2 + k0;
#pragma unroll
            for (int i = 0; i < 4; i++) {
                int c = (tid & 1) * 16 + i * 4;
                float4 v = *(const float4*)(mrow + c);
                Ms[s][c] = v.x * u; Ms[s][c + 1] = v.y * u;
                Ms[s][c + 2] = v.z * u; Ms[s][c + 3] = v.w * u;
            }
        }
        if (tid < 128) {
            int r = tid >> 3, c = (tid & 7) * 4;
            float4 v = *(const float4*)(X + ((size_t)((t0 + r) * BBS + b)) * DD2 + k0 + c);
            Xs[r][c] = v.x; Xs[r][c + 1] = v.y; Xs[r][c + 2] = v.z; Xs[r][c + 3] = v.w;
        }
        __syncthreads();
#pragma unroll
        for (int kk = 0; kk < 32; kk++) {
            float xv = Xs[ti][kk];
#pragma unroll
            for (int u = 0; u < 8; u++) acc[u] += xv * Ms[si * 8 + u][kk];
        }
        __syncthreads();
    }

#pragma unroll
    for (int u = 0; u < 8; u++) acc[u] = tanhf(acc[u] * um[si * 8 + u]);
    float mx = -1e30f;
#pragma unroll
    for (int u = 0; u < 8; u++) mx = fmaxf(mx, acc[u]);
    for (int o = 8; o >= 1; o >>= 1) mx = fmaxf(mx, __shfl_xor_sync(0xffffffffu, mx, o, 16));
    float a[8]; float s2 = 0.0f;
#pragma unroll
    for (int u = 0; u < 8; u++) {
        a[u] = expf(acc[u] - mx) * um[si * 8 + u];
        s2 += a[u];
    }
    for (int o = 8; o >= 1; o >>= 1) s2 += __shfl_xor_sync(0xffffffffu, s2, o, 16);
    float inv = 1.0f / s2;
#pragma unroll
    for (int u = 0; u < 8; u++) Aa[ti][si * 8 + u] = a[u] * inv;
    __syncthreads();

    for (int d0 = 0; d0 < DD2; d0 += 32) {
        {
            int s = tid >> 1;
            const float* mrow = M + ((size_t)(s * BBS + b)) * DD2 + d0;
#pragma unroll
            for (int i = 0; i < 4; i++) {
                int c = (tid & 1) * 16 + i * 4;
                float4 v = *(const float4*)(mrow + c);
                Ms[s][c] = v.x; Ms[s][c + 1] = v.y; Ms[s][c + 2] = v.z; Ms[s][c + 3] = v.w;
            }
        }
        __syncthreads();
        int dloc = (tid & 15) * 2;
        float r0 = 0.f, r1 = 0.f;
#pragma unroll 8
        for (int s = 0; s < 128; s++) {
            float al = Aa[ti][s];
            r0 += al * Ms[s][dloc];
            r1 += al * Ms[s][dloc + 1];
        }
        float* orow = att + ((size_t)((t0 + ti) * BBS + b)) * DD2 + d0 + dloc;
        orow[0] = r0; orow[1] = r1;
        __syncthreads();
    }
}

// ---------------- launch ----------------
extern "C" void kernel_launch(void* const* d_in, const int* in_sizes, int n_in,
                              void* d_out, int out_size) {
    const float* feat   = (const float*)d_in[0];
    const int*   ei     = (const int*)d_in[1];
    const int*   et     = (const int*)d_in[2];
    const float* umask  = (const float*)d_in[4];
    const float* Wrel   = (const float*)d_in[5];
    const float* Wroot  = (const float*)d_in[6];
    const float* rb     = (const float*)d_in[7];
    const float* gcWrel = (const float*)d_in[8];
    const float* gcWroot= (const float*)d_in[9];
    const float* gcb    = (const float*)d_in[10];
    const float* Wih0   = (const float*)d_in[11];
    const float* Whh0   = (const float*)d_in[12];
    const float* b0     = (const float*)d_in[13];
    const float* Wih1   = (const float*)d_in[14];
    const float* Whh1   = (const float*)d_in[15];
    const float* b1     = (const float*)d_in[16];
    const float* mattW  = (const float*)d_in[17];
    const float* mattb  = (const float*)d_in[18];
    const float* linW   = (const float*)d_in[19];
    const float* linb   = (const float*)d_in[20];
    float* out = (float*)d_out;

    float *hrel, *out1, *cnt, *agg, *out2, *x0, *g0, *h0, *g1, *Mb, *Xb, *attb, *barp, *hfp;
    u32 *whi, *wlo;
    cudaGetSymbolAddress((void**)&hrel, g_hrel);
    cudaGetSymbolAddress((void**)&out1, g_out1);
    cudaGetSymbolAddress((void**)&cnt,  g_cnt);
    cudaGetSymbolAddress((void**)&agg,  g_agg);
    cudaGetSymbolAddress((void**)&out2, g_out2);
    cudaGetSymbolAddress((void**)&x0,   g_x0);
    cudaGetSymbolAddress((void**)&g0,   g_g0);
    cudaGetSymbolAddress((void**)&h0,   g_h0);
    cudaGetSymbolAddress((void**)&g1,   g_g1);
    cudaGetSymbolAddress((void**)&Mb,   g_M);
    cudaGetSymbolAddress((void**)&Xb,   g_X);
    cudaGetSymbolAddress((void**)&attb, g_att);
    cudaGetSymbolAddress((void**)&barp, (const void*)g_bar);
    cudaGetSymbolAddress((void**)&whi,  g_whi);
    cudaGetSymbolAddress((void**)&wlo,  g_wlo);
    cudaGetSymbolAddress((void**)&hfp,  g_hf);

    cudaFuncSetAttribute(lstm_tc_kernel,
                         cudaFuncAttributeMaxDynamicSharedMemorySize, SMEM_TLSTM);

    const int WN = 2 * GG4 * DHH;
    const int HSF = 2 * 2 * BBS * DHH;

    // --- graph stage ---
    fill_zero_kernel<<<(NN * RRE + 255) / 256, 256>>>(cnt, NN * RRE);
    fill_zero_kernel<<<(NN * HIDN + 255) / 256, 256>>>(agg, NN * HIDN);
    count_kernel<<<EE / 256, 256>>>(ei, et, cnt);
    tgemm_kernel<false, false><<<dim3(4, 32, 1), 256>>>(feat, Wroot, rb, out1,
        NN, HIDN, FIN, 0, 0, 0, 0, 0);
    tgemm_kernel<false, false><<<dim3(4, 32, RRE), 256>>>(feat, Wrel, nullptr, hrel,
        NN, HIDN, FIN, 0, (size_t)FIN * HIDN, 0, (size_t)NN * HIDN, 0);
    rgcn_scatter_kernel<<<EE / 4, 256>>>(hrel, ei, et, cnt, out1);
    gconv_scatter_kernel<<<EE / 4, 256>>>(out1, ei, agg);
    tgemm_kernel<false, false><<<dim3(4, 32, 1), 256>>>(agg, gcWrel, gcb, out2,
        NN, HIDN, HIDN, 0, 0, 0, 0, 0);
    tgemm_kernel<false, false><<<dim3(4, 32, 1), 256>>>(out1, gcWroot, nullptr, out2,
        NN, HIDN, HIDN, 0, 0, 0, 0, 1);
    concat_kernel<<<NN, 256>>>(feat, out2, x0);

    // --- BiLSTM layer 0 ---
    tgemm_kernel<true, false><<<dim3(48, 32, 2), 256>>>(x0, Wih0, b0, g0,
        NN, GG4, DHH, 0, (size_t)GG4 * DHH, GG4, (size_t)NN * GG4, 0);
    wsplit_kernel<<<(WN + 255) / 256, 256>>>(Whh0, whi, wlo, WN);
    fill_zero_kernel<<<(HSF + 255) / 256, 256>>>(hfp, HSF);
    fill_zero_kernel<<<1, 256>>>(barp, 2);
    lstm_tc_kernel<<<NBLK, 256, SMEM_TLSTM>>>(whi, wlo, g0, hfp, h0);

    // --- BiLSTM layer 1 ---
    tgemm_kernel<true, false><<<dim3(48, 32, 2), 256>>>(h0, Wih1, b1, g1,
        NN, GG4, DD2, 0, (size_t)GG4 * DD2, GG4, (size_t)NN * GG4, 0);
    wsplit_kernel<<<(WN + 255) / 256, 256>>>(Whh1, whi, wlo, WN);
    fill_zero_kernel<<<(HSF + 255) / 256, 256>>>(hfp, HSF);
    fill_zero_kernel<<<1, 256>>>(barp, 2);
    lstm_tc_kernel<<<NBLK, 256, SMEM_TLSTM>>>(whi, wlo, g1, hfp, Mb);

    // --- attention + output ---
    tgemm_kernel<true, false><<<dim3(24, 32, 1), 256>>>(Mb, mattW, mattb, Xb,
        NN, DD2, DD2, 0, 0, 0, 0, 0);
    attention_kernel<<<dim3(8, 32), 256>>>(Mb, Xb, umask, attb);
    tgemm_kernel<true, true><<<dim3(12, 32, 1), 256>>>(attb, linW, linb, out,
        NN, DHH, DD2, 0, 0, 0, 0, 0);
}

// round 12
// speedup vs baseline: 2.8589x; 1.0238x over previous
#include <cuda_runtime.h>
#include <math.h>

#define NN    4096
#define FIN   512
#define HIDN  256
#define RRE   16
#define EE    65536
#define BBS   32
#define SSEQ  128
#define DHH   768
#define DD2   1536
#define GG4   3072

typedef unsigned long long u64;
typedef unsigned int u32;

// ---------------- tf32 helpers ----------------
__device__ __forceinline__ u32 cvtf(float x) {
    u32 r; asm("cvt.rna.tf32.f32 %0, %1;" : "=r"(r) : "f"(x)); return r;
}
__device__ __forceinline__ void split_tf32(float x, u32& hi, u32& lo) {
    hi = cvtf(x);
    lo = cvtf(x - __uint_as_float(hi));
}
__device__ __forceinline__ void mma8(float* d, const u32* a, const u32* b) {
    asm("mma.sync.aligned.m16n8k8.row.col.f32.tf32.tf32.f32 "
        "{%0,%1,%2,%3}, {%4,%5,%6,%7}, {%8,%9}, {%0,%1,%2,%3};"
        : "+f"(d[0]), "+f"(d[1]), "+f"(d[2]), "+f"(d[3])
        : "r"(a[0]), "r"(a[1]), "r"(a[2]), "r"(a[3]), "r"(b[0]), "r"(b[1]));
}
__device__ __forceinline__ void cpa16(u32 dst, const void* src) {
    asm volatile("cp.async.ca.shared.global [%0], [%1], 16;" :: "r"(dst), "l"(src) : "memory");
}

// ---------------- device scratch ----------------
__device__ float g_hrel[(size_t)RRE * NN * HIDN];
__device__ float g_out1[(size_t)NN * HIDN];
__device__ float g_cnt[(size_t)NN * RRE];
__device__ float g_agg[(size_t)NN * HIDN];
__device__ float g_out2[(size_t)NN * HIDN];
__device__ float g_x0[(size_t)NN * DHH];
__device__ float g_g0[(size_t)2 * NN * GG4];
__device__ float g_h0[(size_t)NN * DD2];
__device__ float g_g1[(size_t)2 * NN * GG4];
__device__ float g_M[(size_t)NN * DD2];
__device__ float g_X[(size_t)NN * DD2];
__device__ float g_att[(size_t)NN * DD2];
__device__ u32 g_whi[(size_t)2 * GG4 * DHH];    // Whh tf32 hi
__device__ u32 g_wlo[(size_t)2 * GG4 * DHH];    // Whh tf32 lo
__device__ float g_hf[(size_t)2 * 2 * BBS * DHH]; // h state [parity][dir][b][k], f32
__device__ unsigned g_bar[2];                   // cnt, gen

__global__ void fill_zero_kernel(float* p, int n) {
    int i = blockIdx.x * 256 + threadIdx.x;
    if (i < n) p[i] = 0.0f;
}

__device__ __forceinline__ float sigf(float x) { return 1.0f / (1.0f + expf(-x)); }

// ---------------- 3xTF32 tensor-core GEMM, cp.async double-buffered ----------
template<bool TRANSB, bool RELU>
__global__ __launch_bounds__(256, 2) void tgemm_kernel(
    const float* __restrict__ A, const float* __restrict__ B,
    const float* __restrict__ bias, float* __restrict__ C,
    int M, int N, int K,
    size_t sA, size_t sB, size_t sBias, size_t sC, int addC)
{
    A += (size_t)blockIdx.z * sA;
    B += (size_t)blockIdx.z * sB;
    C += (size_t)blockIdx.z * sC;
    const float* bi = bias ? bias + (size_t)blockIdx.z * sBias : (const float*)0;

    __shared__ __align__(16) float As[2][128 * 20];
    __shared__ __align__(16) float Bs[2][1280];

    const int m0 = blockIdx.y * 128, n0 = blockIdx.x * 64;
    const int tid = threadIdx.x;
    const int lane = tid & 31, wid = tid >> 5;
    const int wm = (wid & 3) * 32, wn = (wid >> 2) * 32;
    const int g = lane >> 2, tig = lane & 3;
    const int KT = K >> 4;

    const u32 sA0 = (u32)__cvta_generic_to_shared(&As[0][0]);
    const u32 sB0 = (u32)__cvta_generic_to_shared(&Bs[0][0]);

    float acc[2][4][4];
#pragma unroll
    for (int mt = 0; mt < 2; mt++)
#pragma unroll
        for (int nt = 0; nt < 4; nt++)
#pragma unroll
            for (int q = 0; q < 4; q++) acc[mt][nt][q] = 0.0f;

    auto issue = [&](int kt, int buf) {
        const int k0 = kt * 16;
        u32 da = sA0 + buf * (128 * 20 * 4);
        {
            int q0 = tid, q1 = tid + 256;
            int ar0 = q0 >> 2, ac0 = (q0 & 3) * 4;
            int ar1 = q1 >> 2, ac1 = (q1 & 3) * 4;
            cpa16(da + (ar0 * 20 + ac0) * 4, A + (size_t)(m0 + ar0) * K + k0 + ac0);
            cpa16(da + (ar1 * 20 + ac1) * 4, A + (size_t)(m0 + ar1) * K + k0 + ac1);
        }
        u32 db = sB0 + buf * (1280 * 4);
        if (TRANSB) {
            int br = tid >> 2, bc = (tid & 3) * 4;
            cpa16(db + (br * 20 + bc) * 4, B + (size_t)(n0 + br) * K + k0 + bc);
        } else {
            int bk = tid >> 4, bn = (tid & 15) * 4;
            cpa16(db + (bk * 68 + bn) * 4, B + (size_t)(k0 + bk) * N + n0 + bn);
        }
        asm volatile("cp.async.commit_group;" ::: "memory");
    };

    issue(0, 0);
    for (int kt = 0; kt < KT; kt++) {
        const int buf = kt & 1;
        if (kt + 1 < KT) {
            issue(kt + 1, buf ^ 1);
            asm volatile("cp.async.wait_group 1;" ::: "memory");
        } else {
            asm volatile("cp.async.wait_group 0;" ::: "memory");
        }
        __syncthreads();

        const float* Ab = &As[buf][0];
        const float* Bb = &Bs[buf][0];
#pragma unroll
        for (int ks = 0; ks < 2; ks++) {
            const int kb = ks * 8;
            u32 afh[2][4], afl[2][4], bfh[4][2], bfl[4][2];
#pragma unroll
            for (int mt = 0; mt < 2; mt++) {
                int r = wm + mt * 16 + g;
                float x0 = Ab[r * 20 + kb + tig];
                float x1 = Ab[(r + 8) * 20 + kb + tig];
                float x2 = Ab[r * 20 + kb + tig + 4];
                float x3 = Ab[(r + 8) * 20 + kb + tig + 4];
                split_tf32(x0, afh[mt][0], afl[mt][0]);
                split_tf32(x1, afh[mt][1], afl[mt][1]);
                split_tf32(x2, afh[mt][2], afl[mt][2]);
                split_tf32(x3, afh[mt][3], afl[mt][3]);
            }
#pragma unroll
            for (int nt = 0; nt < 4; nt++) {
                int c = wn + nt * 8 + g;
                float y0 = TRANSB ? Bb[c * 20 + kb + tig]     : Bb[(kb + tig) * 68 + c];
                float y1 = TRANSB ? Bb[c * 20 + kb + tig + 4] : Bb[(kb + tig + 4) * 68 + c];
                split_tf32(y0, bfh[nt][0], bfl[nt][0]);
                split_tf32(y1, bfh[nt][1], bfl[nt][1]);
            }
#pragma unroll
            for (int mt = 0; mt < 2; mt++)
#pragma unroll
                for (int nt = 0; nt < 4; nt++) {
                    mma8(acc[mt][nt], afl[mt], bfh[nt]);
                    mma8(acc[mt][nt], afh[mt], bfl[nt]);
                    mma8(acc[mt][nt], afh[mt], bfh[nt]);
                }
        }
        __syncthreads();
    }
#pragma unroll
    for (int mt = 0; mt < 2; mt++) {
#pragma unroll
        for (int nt = 0; nt < 4; nt++) {
            int c = n0 + wn + nt * 8 + 2 * tig;
#pragma unroll
            for (int h = 0; h < 2; h++) {
                int r = m0 + wm + mt * 16 + g + h * 8;
                float2 v = make_float2(acc[mt][nt][h * 2], acc[mt][nt][h * 2 + 1]);
                if (bi) { v.x += bi[c]; v.y += bi[c + 1]; }
                float2* cp = (float2*)&C[(size_t)r * N + c];
                if (addC) { float2 o = *cp; v.x += o.x; v.y += o.y; }
                if (RELU) { v.x = fmaxf(v.x, 0.f); v.y = fmaxf(v.y, 0.f); }
                *cp = v;
            }
        }
    }
}

// ---------------- graph kernels ----------------
__global__ void count_kernel(const int* __restrict__ ei, const int* __restrict__ et,
                             float* __restrict__ cnt) {
    int e = blockIdx.x * 256 + threadIdx.x;
    if (e < EE) atomicAdd(&cnt[ei[EE + e] * RRE + et[e]], 1.0f);
}

__global__ void rgcn_scatter_kernel(const float* __restrict__ hrel, const int* __restrict__ ei,
                                    const int* __restrict__ et, const float* __restrict__ cnt,
                                    float* __restrict__ out1) {
    int e = blockIdx.x * 4 + (threadIdx.x >> 6);
    int lane = threadIdx.x & 63;
    int src = ei[e], dst = ei[EE + e], r = et[e];
    float inv = 1.0f / fmaxf(cnt[dst * RRE + r], 1.0f);
    float4 v = ((const float4*)(hrel + ((size_t)r * NN + src) * HIDN))[lane];
    float* o = out1 + (size_t)dst * HIDN + lane * 4;
    atomicAdd(o + 0, v.x * inv);
    atomicAdd(o + 1, v.y * inv);
    atomicAdd(o + 2, v.z * inv);
    atomicAdd(o + 3, v.w * inv);
}

__global__ void gconv_scatter_kernel(const float* __restrict__ out1, const int* __restrict__ ei,
                                     float* __restrict__ agg) {
    int e = blockIdx.x * 4 + (threadIdx.x >> 6);
    int lane = threadIdx.x & 63;
    int src = ei[e], dst = ei[EE + e];
    float4 v = ((const float4*)(out1 + (size_t)src * HIDN))[lane];
    float* o = agg + (size_t)dst * HIDN + lane * 4;
    atomicAdd(o + 0, v.x);
    atomicAdd(o + 1, v.y);
    atomicAdd(o + 2, v.z);
    atomicAdd(o + 3, v.w);
}

__global__ void concat_kernel(const float* __restrict__ feat, const float* __restrict__ out2,
                              float* __restrict__ x0) {
    int n = blockIdx.x;
    int b = n >> 7, s = n & 127;
    float* dstrow = x0 + (size_t)(s * BBS + b) * DHH;
    for (int d = threadIdx.x; d < DHH; d += 256)
        dstrow[d] = (d < FIN) ? feat[(size_t)n * FIN + d] : out2[(size_t)n * HIDN + (d - FIN)];
}

// ---------------- persistent tensor-core BiLSTM (W-hi in smem) ----------------
#define NBLK 128
#define WST  772
#define PCOLS 52
#define SMEM_TLSTM ((48 * WST + 8 * 32 * PCOLS) * 4)

// global barrier: RMW only for arrival; poll via plain volatile load (no LTS
// per-address atomic serialization across 128 pollers).
__device__ __forceinline__ void gbar(unsigned phase) {
    __syncthreads();
    if (threadIdx.x == 0) {
        __threadfence();
        unsigned a = atomicAdd(&g_bar[0], 1u);
        if (a == NBLK - 1u) {
            g_bar[0] = 0u;
            __threadfence();
            atomicExch(&g_bar[1], phase + 1u);
        } else {
            volatile unsigned* gen = &g_bar[1];
            while (*gen <= phase) __nanosleep(32);
        }
        __threadfence();
    }
    __syncthreads();
}

__global__ void wsplit_kernel(const float* __restrict__ W, u32* __restrict__ whi,
                              u32* __restrict__ wlo, int n) {
    int i = blockIdx.x * 256 + threadIdx.x;
    if (i < n) {
        u32 h, l; split_tf32(W[i], h, l);
        whi[i] = h; wlo[i] = l;
    }
}

__global__ __launch_bounds__(256) void lstm_tc_kernel(
    const u32* __restrict__ Whi, const u32* __restrict__ Wlo,
    const float* __restrict__ gpre,
    float* __restrict__ hf, float* __restrict__ hout)
{
    extern __shared__ u32 smu[];
    u32* whi = smu;                              // [48][WST]
    float* part = (float*)(smu + 48 * WST);      // [8][32][PCOLS]

    const int bx = blockIdx.x;
    const int dir = bx & 1;
    const int j0 = (bx >> 1) * 12;
    const int tid = threadIdx.x;
    const int w = tid >> 5, lane = tid & 31;
    const int g = lane >> 2, tig = lane & 3;

    const u32* WhiG = Whi + (size_t)dir * GG4 * DHH;
    const u32* WloG = Wlo + (size_t)dir * GG4 * DHH;

    for (int idx = tid; idx < 48 * DHH; idx += 256) {
        int c = idx / DHH, k = idx % DHH;
        int row = (c / 12) * DHH + j0 + (c % 12);
        whi[c * WST + k] = WhiG[(size_t)row * DHH + k];
    }
    const u32* wlop[6];
    int ccol[6];
#pragma unroll
    for (int nt = 0; nt < 6; nt++) {
        int c = nt * 8 + g;
        int row = (c / 12) * DHH + j0 + (c % 12);
        wlop[nt] = WloG + (size_t)row * DHH;
        ccol[nt] = c;
    }
    __syncthreads();

    float cst[2] = {0.0f, 0.0f};

    for (int t = 0; t < SSEQ; t++) {
        const float* hin = hf + ((size_t)(t & 1) * 2 + dir) * (BBS * DHH);
        float* hOut      = hf + ((size_t)((t + 1) & 1) * 2 + dir) * (BBS * DHH);

        float acc[2][6][4];
#pragma unroll
        for (int mt = 0; mt < 2; mt++)
#pragma unroll
            for (int nt = 0; nt < 6; nt++)
#pragma unroll
                for (int q = 0; q < 4; q++) acc[mt][nt][q] = 0.0f;

        const int kw = w * 96;
#pragma unroll
        for (int s = 0; s < 12; s++) {
            const int k0 = kw + s * 8;
            u32 ah[2][4], al[2][4];
#pragma unroll
            for (int mt = 0; mt < 2; mt++) {
                int r0 = mt * 16 + g;
                float f0 = hin[r0 * DHH + k0 + tig];
                float f1 = hin[(r0 + 8) * DHH + k0 + tig];
                float f2 = hin[r0 * DHH + k0 + tig + 4];
                float f3 = hin[(r0 + 8) * DHH + k0 + tig + 4];
                split_tf32(f0, ah[mt][0], al[mt][0]);
                split_tf32(f1, ah[mt][1], al[mt][1]);
                split_tf32(f2, ah[mt][2], al[mt][2]);
                split_tf32(f3, ah[mt][3], al[mt][3]);
            }
#pragma unroll
            for (int nt = 0; nt < 6; nt++) {
                u32 bh[2], bl[2];
                bh[0] = whi[ccol[nt] * WST + k0 + tig];
                bh[1] = whi[ccol[nt] * WST + k0 + tig + 4];
                bl[0] = wlop[nt][k0 + tig];
                bl[1] = wlop[nt][k0 + tig + 4];
#pragma unroll
                for (int mt = 0; mt < 2; mt++) {
                    mma8(acc[mt][nt], al[mt], bh);
                    mma8(acc[mt][nt], ah[mt], bl);
                    mma8(acc[mt][nt], ah[mt], bh);
                }
            }
        }
        // store K-partials
#pragma unroll
        for (int mt = 0; mt < 2; mt++)
#pragma unroll
            for (int nt = 0; nt < 6; nt++) {
                int b0 = mt * 16 + g, c = nt * 8 + 2 * tig;
                float* p0 = &part[(w * 32 + b0) * PCOLS + c];
                p0[0] = acc[mt][nt][0]; p0[1] = acc[mt][nt][1];
                float* p1 = &part[(w * 32 + b0 + 8) * PCOLS + c];
                p1[0] = acc[mt][nt][2]; p1[1] = acc[mt][nt][3];
            }
        __syncthreads();
        // fused reduce + gate nonlinearity + state update (384 (b,jl) pairs)
        const int tdir = dir ? (SSEQ - 1 - t) : t;
#pragma unroll
        for (int u = 0; u < 2; u++) {
            int pr = tid + u * 256;
            if (pr < 384) {
                int b = pr / 12, jl = pr % 12;
                int j = j0 + jl;
                int row = tdir * BBS + b;
                const float* gp = gpre + ((size_t)dir * NN + row) * GG4;
                float gi = 0.f, gf = 0.f, gg = 0.f, go = 0.f;
#pragma unroll
                for (int ww = 0; ww < 8; ww++) {
                    const float* p = &part[(ww * 32 + b) * PCOLS];
                    gi += p[jl];
                    gf += p[12 + jl];
                    gg += p[24 + jl];
                    go += p[36 + jl];
                }
                gi += gp[j];
                gf += gp[DHH + j];
                gg += gp[2 * DHH + j];
                go += gp[3 * DHH + j];
                float c2 = sigf(gf) * cst[u] + sigf(gi) * tanhf(gg);
                cst[u] = c2;
                float h = sigf(go) * tanhf(c2);
                hout[(size_t)row * DD2 + dir * DHH + j] = h;
                hOut[b * DHH + j] = h;
            }
        }
        gbar((unsigned)t);
    }
}

// ---------------- attention ----------------
__global__ __launch_bounds__(256) void attention_kernel(
    const float* __restrict__ M, const float* __restrict__ X,
    const float* __restrict__ umask, float* __restrict__ att)
{
    const int b = blockIdx.y;
    const int t0 = blockIdx.x * 16;
    const int tid = threadIdx.x;
    const int ti = tid >> 4, si = tid & 15;

    __shared__ float Ms[128][33];
    __shared__ float Xs[16][33];
    __shared__ float Aa[16][129];
    __shared__ float um[128];
    if (tid < 128) um[tid] = umask[b * SSEQ + tid];
    __syncthreads();

    float acc[8];
#pragma unroll
    for (int u = 0; u < 8; u++) acc[u] = 0.0f;

    for (int k0 = 0; k0 < DD2; k0 += 32) {
        {
            int s = tid >> 1;
            float u = um[s];
            const float* mrow = M + ((size_t)(s * BBS + b)) * DD2 + k0;
#pragma unroll
            for (int i = 0; i < 4; i++) {
                int c = (tid & 1) * 16 + i * 4;
                float4 v = *(const float4*)(mrow + c);
                Ms[s][c] = v.x * u; Ms[s][c + 1] = v.y * u;
                Ms[s][c + 2] = v.z * u; Ms[s][c + 3] = v.w * u;
            }
        }
        if (tid < 128) {
            int r = tid >> 3, c = (tid & 7) * 4;
            float4 v = *(const float4*)(X + ((size_t)((t0 + r) * BBS + b)) * DD2 + k0 + c);
            Xs[r][c] = v.x; Xs[r][c + 1] = v.y; Xs[r][c + 2] = v.z; Xs[r][c + 3] = v.w;
        }
        __syncthreads();
#pragma unroll
        for (int kk = 0; kk < 32; kk++) {
            float xv = Xs[ti][kk];
#pragma unroll
            for (int u = 0; u < 8; u++) acc[u] += xv * Ms[si * 8 + u][kk];
        }
        __syncthreads();
    }

#pragma unroll
    for (int u = 0; u < 8; u++) acc[u] = tanhf(acc[u] * um[si * 8 + u]);
    float mx = -1e30f;
#pragma unroll
    for (int u = 0; u < 8; u++) mx = fmaxf(mx, acc[u]);
    for (int o = 8; o >= 1; o >>= 1) mx = fmaxf(mx, __shfl_xor_sync(0xffffffffu, mx, o, 16));
    float a[8]; float s2 = 0.0f;
#pragma unroll
    for (int u = 0; u < 8; u++) {
        a[u] = expf(acc[u] - mx) * um[si * 8 + u];
        s2 += a[u];
    }
    for (int o = 8; o >= 1; o >>= 1) s2 += __shfl_xor_sync(0xffffffffu, s2, o, 16);
    float inv = 1.0f / s2;
#pragma unroll
    for (int u = 0; u < 8; u++) Aa[ti][si * 8 + u] = a[u] * inv;
    __syncthreads();

    for (int d0 = 0; d0 < DD2; d0 += 32) {
        {
            int s = tid >> 1;
            const float* mrow = M + ((size_t)(s * BBS + b)) * DD2 + d0;
#pragma unroll
            for (int i = 0; i < 4; i++) {
                int c = (tid & 1) * 16 + i * 4;
                float4 v = *(const float4*)(mrow + c);
                Ms[s][c] = v.x; Ms[s][c + 1] = v.y; Ms[s][c + 2] = v.z; Ms[s][c + 3] = v.w;
            }
        }
        __syncthreads();
        int dloc = (tid & 15) * 2;
        float r0 = 0.f, r1 = 0.f;
#pragma unroll 8
        for (int s = 0; s < 128; s++) {
            float al = Aa[ti][s];
            r0 += al * Ms[s][dloc];
            r1 += al * Ms[s][dloc + 1];
        }
        float* orow = att + ((size_t)((t0 + ti) * BBS + b)) * DD2 + d0 + dloc;
        orow[0] = r0; orow[1] = r1;
        __syncthreads();
    }
}

// ---------------- launch ----------------
extern "C" void kernel_launch(void* const* d_in, const int* in_sizes, int n_in,
                              void* d_out, int out_size) {
    const float* feat   = (const float*)d_in[0];
    const int*   ei     = (const int*)d_in[1];
    const int*   et     = (const int*)d_in[2];
    const float* umask  = (const float*)d_in[4];
    const float* Wrel   = (const float*)d_in[5];
    const float* Wroot  = (const float*)d_in[6];
    const float* rb     = (const float*)d_in[7];
    const float* gcWrel = (const float*)d_in[8];
    const float* gcWroot= (const float*)d_in[9];
    const float* gcb    = (const float*)d_in[10];
    const float* Wih0   = (const float*)d_in[11];
    const float* Whh0   = (const float*)d_in[12];
    const float* b0     = (const float*)d_in[13];
    const float* Wih1   = (const float*)d_in[14];
    const float* Whh1   = (const float*)d_in[15];
    const float* b1     = (const float*)d_in[16];
    const float* mattW  = (const float*)d_in[17];
    const float* mattb  = (const float*)d_in[18];
    const float* linW   = (const float*)d_in[19];
    const float* linb   = (const float*)d_in[20];
    float* out = (float*)d_out;

    float *hrel, *out1, *cnt, *agg, *out2, *x0, *g0, *h0, *g1, *Mb, *Xb, *attb, *barp, *hfp;
    u32 *whi, *wlo;
    cudaGetSymbolAddress((void**)&hrel, g_hrel);
    cudaGetSymbolAddress((void**)&out1, g_out1);
    cudaGetSymbolAddress((void**)&cnt,  g_cnt);
    cudaGetSymbolAddress((void**)&agg,  g_agg);
    cudaGetSymbolAddress((void**)&out2, g_out2);
    cudaGetSymbolAddress((void**)&x0,   g_x0);
    cudaGetSymbolAddress((void**)&g0,   g_g0);
    cudaGetSymbolAddress((void**)&h0,   g_h0);
    cudaGetSymbolAddress((void**)&g1,   g_g1);
    cudaGetSymbolAddress((void**)&Mb,   g_M);
    cudaGetSymbolAddress((void**)&Xb,   g_X);
    cudaGetSymbolAddress((void**)&attb, g_att);
    cudaGetSymbolAddress((void**)&barp, (const void*)g_bar);
    cudaGetSymbolAddress((void**)&whi,  g_whi);
    cudaGetSymbolAddress((void**)&wlo,  g_wlo);
    cudaGetSymbolAddress((void**)&hfp,  g_hf);

    cudaFuncSetAttribute(lstm_tc_kernel,
                         cudaFuncAttributeMaxDynamicSharedMemorySize, SMEM_TLSTM);

    const int WN = 2 * GG4 * DHH;
    const int HSF = 2 * 2 * BBS * DHH;

    // --- graph stage ---
    fill_zero_kernel<<<(NN * RRE + 255) / 256, 256>>>(cnt, NN * RRE);
    fill_zero_kernel<<<(NN * HIDN + 255) / 256, 256>>>(agg, NN * HIDN);
    count_kernel<<<EE / 256, 256>>>(ei, et, cnt);
    tgemm_kernel<false, false><<<dim3(4, 32, 1), 256>>>(feat, Wroot, rb, out1,
        NN, HIDN, FIN, 0, 0, 0, 0, 0);
    tgemm_kernel<false, false><<<dim3(4, 32, RRE), 256>>>(feat, Wrel, nullptr, hrel,
        NN, HIDN, FIN, 0, (size_t)FIN * HIDN, 0, (size_t)NN * HIDN, 0);
    rgcn_scatter_kernel<<<EE / 4, 256>>>(hrel, ei, et, cnt, out1);
    gconv_scatter_kernel<<<EE / 4, 256>>>(out1, ei, agg);
    tgemm_kernel<false, false><<<dim3(4, 32, 1), 256>>>(agg, gcWrel, gcb, out2,
        NN, HIDN, HIDN, 0, 0, 0, 0, 0);
    tgemm_kernel<false, false><<<dim3(4, 32, 1), 256>>>(out1, gcWroot, nullptr, out2,
        NN, HIDN, HIDN, 0, 0, 0, 0, 1);
    concat_kernel<<<NN, 256>>>(feat, out2, x0);

    // --- BiLSTM layer 0 ---
    tgemm_kernel<true, false><<<dim3(48, 32, 2), 256>>>(x0, Wih0, b0, g0,
        NN, GG4, DHH, 0, (size_t)GG4 * DHH, GG4, (size_t)NN * GG4, 0);
    wsplit_kernel<<<(WN + 255) / 256, 256>>>(Whh0, whi, wlo, WN);
    fill_zero_kernel<<<(HSF + 255) / 256, 256>>>(hfp, HSF);
    fill_zero_kernel<<<1, 256>>>(barp, 2);
    lstm_tc_kernel<<<NBLK, 256, SMEM_TLSTM>>>(whi, wlo, g0, hfp, h0);

    // --- BiLSTM layer 1 ---
    tgemm_kernel<true, false><<<dim3(48, 32, 2), 256>>>(h0, Wih1, b1, g1,
        NN, GG4, DD2, 0, (size_t)GG4 * DD2, GG4, (size_t)NN * GG4, 0);
    wsplit_kernel<<<(WN + 255) / 256, 256>>>(Whh1, whi, wlo, WN);
    fill_zero_kernel<<<(HSF + 255) / 256, 256>>>(hfp, HSF);
    fill_zero_kernel<<<1, 256>>>(barp, 2);
    lstm_tc_kernel<<<NBLK, 256, SMEM_TLSTM>>>(whi, wlo, g1, hfp, Mb);

    // --- attention + output ---
    tgemm_kernel<true, false><<<dim3(24, 32, 1), 256>>>(Mb, mattW, mattb, Xb,
        NN, DD2, DD2, 0, 0, 0, 0, 0);
    attention_kernel<<<dim3(8, 32), 256>>>(Mb, Xb, umask, attb);
    tgemm_kernel<true, true><<<dim3(12, 32, 1), 256>>>(attb, linW, linb, out,
        NN, DHH, DD2, 0, 0, 0, 0, 0);
}